// round 1
// baseline (speedup 1.0000x reference)
#include <cuda_runtime.h>
#include <math.h>

// Fixed problem dims (B=4, N=512, C=128, ED=64, ATT=8, IN=128)
#define MAXB 4
#define MAXNM 511

// ---------------- scratch (device globals; no allocation allowed) ----------
__device__ float d_M[MAXB * 128 * 128];       // folded q*Wk matrix per batch
__device__ float d_c[MAXB * 128];             // folded q*Wk_b
__device__ float d_e[MAXB * MAXNM * 64];      // e = h[:,0,1:,:]
__device__ float d_logits[MAXB * MAXNM * 128];// logits -> alpha (in place)
__device__ float d_etr[MAXB * MAXNM * 128];   // e@et_w.T + et_b (pre-alpha)
__device__ float d_ntr[MAXB * MAXNM * 128];   // node@nt_w.T + nt_b (pre-alpha)
__device__ float d_g[MAXB * MAXNM * 128];     // gelu hidden

__device__ __forceinline__ float geluf(float x) {
    return 0.5f * x * (1.0f + erff(x * 0.7071067811865476f));
}
__device__ __forceinline__ float rhof(float x) {
    return copysignf(sqrtf(fabsf(x)), x);
}
__device__ __forceinline__ float dot4(float4 a, float4 b) {
    return a.x * b.x + a.y * b.y + a.z * b.z + a.w * b.w;
}

// ---------------------------------------------------------------------------
// K1: fold q into M[b,e,d] = sum_a q[b,a*128+e] * Wk_w[(a*128+e), d]
//     and c[b,e] = sum_a q[b,a*128+e] * Wk_b[a*128+e]
// grid = B*8 (each block: one batch, 16-wide e-slice), block = 128
// ---------------------------------------------------------------------------
__global__ void k1_fold(const float* __restrict__ node,
                        const float* __restrict__ Wq_w, const float* __restrict__ Wq_b,
                        const float* __restrict__ Wk_w, const float* __restrict__ Wk_b,
                        int N) {
    int b = blockIdx.x >> 3;
    int s = blockIdx.x & 7;
    int e0 = s * 16;
    int t = threadIdx.x;

    __shared__ float nd0[128];
    __shared__ float qsh[8][16];

    if (t < 128) nd0[t] = node[(size_t)b * N * 128 + t];
    __syncthreads();

    // q for (a, e-local): 128 values, one per thread
    {
        int a = t >> 4, el = t & 15;
        int row = (a << 7) + e0 + el;
        const float* w = Wq_w + (size_t)row * 128;
        float acc = Wq_b[row];
#pragma unroll 4
        for (int d = 0; d < 128; d++) acc += nd0[d] * w[d];
        qsh[a][el] = acc;
    }
    __syncthreads();

    // M slice: thread t = column d, loop 16 e's
    for (int el = 0; el < 16; el++) {
        int e = e0 + el;
        float acc = 0.f;
#pragma unroll
        for (int a = 0; a < 8; a++)
            acc += qsh[a][el] * Wk_w[(size_t)((a << 7) + e) * 128 + t];
        d_M[(size_t)b * 16384 + e * 128 + t] = acc;
    }
    if (t < 16) {
        int e = e0 + t;
        float acc = 0.f;
#pragma unroll
        for (int a = 0; a < 8; a++) acc += qsh[a][t] * Wk_b[(a << 7) + e];
        d_c[b * 128 + e] = acc;
    }
}

// ---------------------------------------------------------------------------
// K2: qk[n,e] = node[b,n] . M[b,e] + c[b,e];
//     h[n,j] = gelu(rho(qk[j]*ew[j]) + eb[j] + qk[64+j] + emb[b,0,n,j])
//     store e rows (n = 1..N-1) -> d_e
// grid = B*nblk (16 rows each), block = 128
// smem floats: Ms 128*132 | We 64*68 | Wb 64*68 | nds 16*128 | e0s 16*64
//              | ems 16*64 | cs 128 | qks 16*128   = 31872 floats
// ---------------------------------------------------------------------------
__global__ void k2_edgeattn(const float* __restrict__ node,
                            const float* __restrict__ edge,
                            const float* __restrict__ emb,
                            const float* __restrict__ Wew,
                            const float* __restrict__ Web,
                            int N, int nblk) {
    extern __shared__ float sm[];
    float* Ms  = sm;                    // 128*132
    float* Wes = Ms + 128 * 132;        // 64*68
    float* Wbs = Wes + 64 * 68;         // 64*68
    float* nds = Wbs + 64 * 68;         // 16*128
    float* e0s = nds + 16 * 128;        // 16*64
    float* ems = e0s + 16 * 64;         // 16*64
    float* cs  = ems + 16 * 64;         // 128
    float* qks = cs + 128;              // 16*128

    int b  = blockIdx.x / nblk;
    int m0 = (blockIdx.x % nblk) * 16;
    int t  = threadIdx.x;
    int NM = N - 1;

    for (int idx = t; idx < 128 * 128; idx += 128) {
        int e = idx >> 7, d = idx & 127;
        Ms[e * 132 + d] = d_M[(size_t)b * 16384 + idx];
    }
    for (int idx = t; idx < 64 * 64; idx += 128) {
        int j = idx >> 6, d = idx & 63;
        Wes[j * 68 + d] = Wew[idx];
        Wbs[j * 68 + d] = Web[idx];
    }
    cs[t] = d_c[b * 128 + t];
    for (int idx = t; idx < 16 * 128; idx += 128) {
        int r = idx >> 7, d = idx & 127;
        int m = m0 + r;
        nds[idx] = (m < NM) ? node[((size_t)b * N + (m + 1)) * 128 + d] : 0.f;
    }
    for (int idx = t; idx < 16 * 64; idx += 128) {
        int r = idx >> 6, j = idx & 63;
        int m = m0 + r;
        size_t base = ((size_t)b * N * N + (size_t)(m + 1)) * 64;
        e0s[idx] = (m < NM) ? edge[base + j] : 0.f;
        ems[idx] = (m < NM) ? emb[base + j] : 0.f;
    }
    __syncthreads();

    // qk: thread = output column e, 16 rows
    {
        int e = t;
        float acc[16];
#pragma unroll
        for (int r = 0; r < 16; r++) acc[r] = 0.f;
        for (int d4 = 0; d4 < 32; d4++) {
            float4 m4 = *(const float4*)&Ms[e * 132 + 4 * d4];
#pragma unroll
            for (int r = 0; r < 16; r++) {
                float4 n4 = *(const float4*)&nds[r * 128 + 4 * d4];
                acc[r] += dot4(m4, n4);
            }
        }
        float ce = cs[e];
#pragma unroll
        for (int r = 0; r < 16; r++) qks[r * 128 + e] = acc[r] + ce;
    }
    __syncthreads();

    // h: thread = (j = t&63, half = t>>6 handles 8 rows)
    {
        int j = t & 63, half = t >> 6;
        for (int rr = 0; rr < 8; rr++) {
            int r = half * 8 + rr;
            int m = m0 + r;
            if (m >= NM) continue;
            float ew = 0.f, eb = 0.f;
            for (int d4 = 0; d4 < 16; d4++) {
                float4 w4 = *(const float4*)&Wes[j * 68 + 4 * d4];
                float4 b4 = *(const float4*)&Wbs[j * 68 + 4 * d4];
                float4 x4 = *(const float4*)&e0s[r * 64 + 4 * d4];
                ew += dot4(w4, x4);
                eb += dot4(b4, x4);
            }
            float x = rhof(qks[r * 128 + j] * ew) + eb + qks[r * 128 + 64 + j] + ems[r * 64 + j];
            d_e[((size_t)b * NM + m) * 64 + j] = geluf(x);
        }
    }
}

// ---------------------------------------------------------------------------
// K3: logits = e@Wa.T ; etr = e@et_w.T + et_b ; ntr = node@nt_w.T + nt_b
// grid = B*nblk, block = 128 (thread = output i)
// smem: Wa 128*68 | etw 128*68 | ntw 128*132 | er 16*64 | ndr 16*128 = 37376
// ---------------------------------------------------------------------------
__global__ void k3_proj(const float* __restrict__ node,
                        const float* __restrict__ Wa,
                        const float* __restrict__ nt_w, const float* __restrict__ nt_b,
                        const float* __restrict__ et_w, const float* __restrict__ et_b,
                        int N, int nblk) {
    extern __shared__ float sm[];
    float* Was = sm;                  // 128*68
    float* ews = Was + 128 * 68;      // 128*68
    float* nts = ews + 128 * 68;      // 128*132
    float* er  = nts + 128 * 132;     // 16*64
    float* ndr = er + 16 * 64;        // 16*128

    int b  = blockIdx.x / nblk;
    int m0 = (blockIdx.x % nblk) * 16;
    int t  = threadIdx.x;
    int NM = N - 1;

    for (int idx = t; idx < 128 * 64; idx += 128) {
        int i = idx >> 6, d = idx & 63;
        Was[i * 68 + d] = Wa[idx];
        ews[i * 68 + d] = et_w[idx];
    }
    for (int idx = t; idx < 128 * 128; idx += 128) {
        int i = idx >> 7, d = idx & 127;
        nts[i * 132 + d] = nt_w[idx];
    }
    for (int idx = t; idx < 16 * 64; idx += 128) {
        int r = idx >> 6, d = idx & 63;
        int m = m0 + r;
        er[idx] = (m < NM) ? d_e[((size_t)b * NM + m) * 64 + d] : 0.f;
    }
    for (int idx = t; idx < 16 * 128; idx += 128) {
        int r = idx >> 7, d = idx & 127;
        int m = m0 + r;
        ndr[idx] = (m < NM) ? node[((size_t)b * N + (m + 1)) * 128 + d] : 0.f;
    }
    __syncthreads();

    float be = et_b[t];
    float bn = nt_b[t];

    for (int ch = 0; ch < 2; ch++) {
        float aa[8], ae[8], an[8];
#pragma unroll
        for (int r = 0; r < 8; r++) { aa[r] = 0.f; ae[r] = 0.f; an[r] = 0.f; }
        for (int d4 = 0; d4 < 16; d4++) {
            float4 wa4 = *(const float4*)&Was[t * 68 + 4 * d4];
            float4 we4 = *(const float4*)&ews[t * 68 + 4 * d4];
#pragma unroll
            for (int r = 0; r < 8; r++) {
                float4 x4 = *(const float4*)&er[(ch * 8 + r) * 64 + 4 * d4];
                aa[r] += dot4(wa4, x4);
                ae[r] += dot4(we4, x4);
            }
        }
        for (int d4 = 0; d4 < 32; d4++) {
            float4 wn4 = *(const float4*)&nts[t * 132 + 4 * d4];
#pragma unroll
            for (int r = 0; r < 8; r++) {
                float4 x4 = *(const float4*)&ndr[(ch * 8 + r) * 128 + 4 * d4];
                an[r] += dot4(wn4, x4);
            }
        }
#pragma unroll
        for (int r = 0; r < 8; r++) {
            int m = m0 + ch * 8 + r;
            if (m < NM) {
                size_t o = ((size_t)b * NM + m) * 128 + t;
                d_logits[o] = aa[r];
                d_etr[o]    = ae[r] + be;
                d_ntr[o]    = an[r] + bn;
            }
        }
    }
}

// ---------------------------------------------------------------------------
// K4: softmax over axis=1 (the NM rows) per (b, i). In-place on d_logits.
// grid = B, block = 1024 (8 row-chunks x 128 cols)
// ---------------------------------------------------------------------------
__global__ void k4_softmax(int NM) {
    int b = blockIdx.x;
    int t = threadIdx.x;
    int i = t & 127, c = t >> 7;  // c in 0..7
    __shared__ float red[8 * 128];
    __shared__ float fm[128];
    __shared__ float fs[128];

    float* base = d_logits + (size_t)b * NM * 128;

    float mx = -3.4e38f;
    for (int m = c; m < NM; m += 8) mx = fmaxf(mx, base[m * 128 + i]);
    red[c * 128 + i] = mx;
    __syncthreads();
    if (c == 0) {
        float v = red[i];
#pragma unroll
        for (int cc = 1; cc < 8; cc++) v = fmaxf(v, red[cc * 128 + i]);
        fm[i] = v;
    }
    __syncthreads();
    float mv = fm[i];

    float s = 0.f;
    for (int m = c; m < NM; m += 8) s += expf(base[m * 128 + i] - mv);
    red[c * 128 + i] = s;
    __syncthreads();
    if (c == 0) {
        float v = 0.f;
#pragma unroll
        for (int cc = 0; cc < 8; cc++) v += red[cc * 128 + i];
        fs[i] = v;
    }
    __syncthreads();
    float inv = 1.f / fs[i];

    for (int m = c; m < NM; m += 8)
        base[m * 128 + i] = expf(base[m * 128 + i] - mv) * inv;
}

// ---------------------------------------------------------------------------
// K5a: v = [etr*alpha | ntr*alpha]; g = gelu(v @ h1_w.T + h1_b); also store
//      et_p[b,i,0,m] = v[m, i] (i < 128).
// grid = B*nblk, block = 128; smem: h1s 128*260 | v 16*256 = 37376 floats
// ---------------------------------------------------------------------------
__global__ void k5a_h1(const float* __restrict__ h1_w, const float* __restrict__ h1_b,
                       float* __restrict__ out_et, int N, int nblk) {
    extern __shared__ float sm[];
    float* h1s = sm;                 // 128*260
    float* v   = h1s + 128 * 260;    // 16*256

    int b  = blockIdx.x / nblk;
    int m0 = (blockIdx.x % nblk) * 16;
    int t  = threadIdx.x;
    int NM = N - 1;

    for (int idx = t; idx < 128 * 256; idx += 128) {
        int jo = idx >> 8, d = idx & 255;
        h1s[jo * 260 + d] = h1_w[idx];
    }
    for (int idx = t; idx < 16 * 256; idx += 128) {
        int r = idx >> 8, d = idx & 255;
        int m = m0 + r;
        float val = 0.f;
        if (m < NM) {
            size_t o = ((size_t)b * NM + m) * 128;
            int dd = d & 127;
            float al = d_logits[o + dd];
            val = ((d < 128) ? d_etr[o + dd] : d_ntr[o + dd]) * al;
        }
        v[idx] = val;
    }
    __syncthreads();

    // et_p output (transposed): thread = i
    {
        int i = t;
#pragma unroll
        for (int r = 0; r < 16; r++) {
            int m = m0 + r;
            if (m < NM)
                out_et[((size_t)b * 128 + i) * NM + m] = v[r * 256 + i];
        }
    }

    float bj = h1_b[t];
    for (int ch = 0; ch < 2; ch++) {
        float acc[8];
#pragma unroll
        for (int r = 0; r < 8; r++) acc[r] = 0.f;
        for (int d4 = 0; d4 < 64; d4++) {
            float4 w4 = *(const float4*)&h1s[t * 260 + 4 * d4];
#pragma unroll
            for (int r = 0; r < 8; r++) {
                float4 x4 = *(const float4*)&v[(ch * 8 + r) * 256 + 4 * d4];
                acc[r] += dot4(w4, x4);
            }
        }
#pragma unroll
        for (int r = 0; r < 8; r++) {
            int m = m0 + ch * 8 + r;
            if (m < NM)
                d_g[((size_t)b * NM + m) * 128 + t] = geluf(acc[r] + bj);
        }
    }
}

// ---------------------------------------------------------------------------
// K5b: tmp = g @ h2_w.T + h2_b ; store tmp_p[b,i,0,m]
// grid = B*nblk, block = 128; smem: h2s 128*132 | gr 16*128 = 18944 floats
// ---------------------------------------------------------------------------
__global__ void k5b_h2(const float* __restrict__ h2_w, const float* __restrict__ h2_b,
                       float* __restrict__ out_tmp, int N, int nblk) {
    extern __shared__ float sm[];
    float* h2s = sm;                 // 128*132
    float* gr  = h2s + 128 * 132;    // 16*128

    int b  = blockIdx.x / nblk;
    int m0 = (blockIdx.x % nblk) * 16;
    int t  = threadIdx.x;
    int NM = N - 1;

    for (int idx = t; idx < 128 * 128; idx += 128) {
        int i = idx >> 7, d = idx & 127;
        h2s[i * 132 + d] = h2_w[idx];
    }
    for (int idx = t; idx < 16 * 128; idx += 128) {
        int r = idx >> 7, d = idx & 127;
        int m = m0 + r;
        gr[idx] = (m < NM) ? d_g[((size_t)b * NM + m) * 128 + d] : 0.f;
    }
    __syncthreads();

    float bi = h2_b[t];
    for (int ch = 0; ch < 2; ch++) {
        float acc[8];
#pragma unroll
        for (int r = 0; r < 8; r++) acc[r] = 0.f;
        for (int d4 = 0; d4 < 32; d4++) {
            float4 w4 = *(const float4*)&h2s[t * 132 + 4 * d4];
#pragma unroll
            for (int r = 0; r < 8; r++) {
                float4 x4 = *(const float4*)&gr[(ch * 8 + r) * 128 + 4 * d4];
                acc[r] += dot4(w4, x4);
            }
        }
#pragma unroll
        for (int r = 0; r < 8; r++) {
            int m = m0 + ch * 8 + r;
            if (m < NM)
                out_tmp[((size_t)b * 128 + t) * NM + m] = acc[r] + bi;
        }
    }
}

// ---------------------------------------------------------------------------
// K6: node_out[b,i] = scaler * sum_m tmp[b,m,i]   (reads transposed tmp_p rows)
// grid = B*128, block = 128
// ---------------------------------------------------------------------------
__global__ void k6_rowsum(const float* __restrict__ tmp_p, float* __restrict__ out_node,
                          int NM, float scaler) {
    int bi = blockIdx.x;
    const float* row = tmp_p + (size_t)bi * NM;
    float s = 0.f;
    for (int m = threadIdx.x; m < NM; m += 128) s += row[m];
#pragma unroll
    for (int o = 16; o > 0; o >>= 1) s += __shfl_down_sync(0xffffffffu, s, o);
    __shared__ float red[4];
    if ((threadIdx.x & 31) == 0) red[threadIdx.x >> 5] = s;
    __syncthreads();
    if (threadIdx.x == 0)
        out_node[bi] = (red[0] + red[1] + red[2] + red[3]) * scaler;
}

// ---------------------------------------------------------------------------
extern "C" void kernel_launch(void* const* d_in, const int* in_sizes, int n_in,
                              void* d_out, int out_size) {
    const float* node   = (const float*)d_in[0];
    const float* edge   = (const float*)d_in[1];
    const float* emb    = (const float*)d_in[2];
    const float* Wq_w   = (const float*)d_in[3];
    const float* Wq_b   = (const float*)d_in[4];
    const float* Wk_w   = (const float*)d_in[5];
    const float* Wk_b   = (const float*)d_in[6];
    const float* Wew    = (const float*)d_in[7];
    const float* Web    = (const float*)d_in[8];
    const float* Wa     = (const float*)d_in[9];
    const float* nt_w   = (const float*)d_in[10];
    const float* nt_b   = (const float*)d_in[11];
    const float* et_w   = (const float*)d_in[12];
    const float* et_b   = (const float*)d_in[13];
    const float* h1_w   = (const float*)d_in[14];
    const float* h1_b   = (const float*)d_in[15];
    const float* h2_w   = (const float*)d_in[16];
    const float* h2_b   = (const float*)d_in[17];

    long n_node = in_sizes[0];
    long n_edge = in_sizes[1];
    int N = (int)((2L * n_edge) / n_node);   // N = 512
    int B = (int)(n_node / ((long)N * 128)); // B = 4
    int NM = N - 1;
    int nblk = (NM + 15) / 16;

    float* out      = (float*)d_out;
    float* out_node = out;
    float* out_tmp  = out + (size_t)B * 128;
    float* out_et   = out_tmp + (size_t)B * 128 * NM;

    const int SM2  = 31872 * 4;
    const int SM3  = 37376 * 4;
    const int SM5A = 37376 * 4;
    const int SM5B = 18944 * 4;

    cudaFuncSetAttribute(k2_edgeattn, cudaFuncAttributeMaxDynamicSharedMemorySize, SM2);
    cudaFuncSetAttribute(k3_proj,     cudaFuncAttributeMaxDynamicSharedMemorySize, SM3);
    cudaFuncSetAttribute(k5a_h1,      cudaFuncAttributeMaxDynamicSharedMemorySize, SM5A);
    cudaFuncSetAttribute(k5b_h2,      cudaFuncAttributeMaxDynamicSharedMemorySize, SM5B);

    k1_fold<<<B * 8, 128>>>(node, Wq_w, Wq_b, Wk_w, Wk_b, N);
    k2_edgeattn<<<B * nblk, 128, SM2>>>(node, edge, emb, Wew, Web, N, nblk);
    k3_proj<<<B * nblk, 128, SM3>>>(node, Wa, nt_w, nt_b, et_w, et_b, N, nblk);
    k4_softmax<<<B, 1024>>>(NM);
    k5a_h1<<<B * nblk, 128, SM5A>>>(h1_w, h1_b, out_et, N, nblk);
    k5b_h2<<<B * nblk, 128, SM5B>>>(h2_w, h2_b, out_tmp, N, nblk);

    float scaler = 2.0f / sqrtf(128.0f);
    k6_rowsum<<<B * 128, 128>>>(out_tmp, out_node, NM, scaler);
}

// round 2
// speedup vs baseline: 1.9285x; 1.9285x over previous
#include <cuda_runtime.h>
#include <math.h>

// Fixed problem dims (B=4, N=512, C=128, ED=64, ATT=8, IN=128)
#define MAXB 4
#define MAXNM 511
#define MAXCH 32

// ---------------- scratch (device globals) ----------------
__device__ float d_M[MAXB * 128 * 128];
__device__ float d_c[MAXB * 128];
__device__ float d_e[MAXB * MAXNM * 64];
__device__ float d_logits[MAXB * MAXNM * 128];
__device__ float d_etr[MAXB * MAXNM * 128];
__device__ float d_ntr[MAXB * MAXNM * 128];
__device__ float d_g[MAXB * MAXNM * 128];
__device__ float d_pm[MAXB * MAXCH * 128];
__device__ float d_ps[MAXB * MAXCH * 128];
__device__ float d_mx[MAXB * 128];
__device__ float d_inv[MAXB * 128];

__device__ __forceinline__ float geluf(float x) {
    return 0.5f * x * (1.0f + erff(x * 0.7071067811865476f));
}
__device__ __forceinline__ float rhof(float x) {
    return copysignf(sqrtf(fabsf(x)), x);
}
__device__ __forceinline__ float dot4(float4 a, float4 b) {
    return a.x * b.x + a.y * b.y + a.z * b.z + a.w * b.w;
}

// ---------------------------------------------------------------------------
// K1: fold q into M[b,e,d] and c[b,e]
// ---------------------------------------------------------------------------
__global__ void k1_fold(const float* __restrict__ node,
                        const float* __restrict__ Wq_w, const float* __restrict__ Wq_b,
                        const float* __restrict__ Wk_w, const float* __restrict__ Wk_b,
                        int N) {
    int b = blockIdx.x >> 3;
    int s = blockIdx.x & 7;
    int e0 = s * 16;
    int t = threadIdx.x;

    __shared__ float nd0[128];
    __shared__ float qsh[8][16];

    if (t < 128) nd0[t] = node[(size_t)b * N * 128 + t];
    __syncthreads();

    {
        int a = t >> 4, el = t & 15;
        int row = (a << 7) + e0 + el;
        const float* w = Wq_w + (size_t)row * 128;
        float acc = Wq_b[row];
#pragma unroll 4
        for (int d = 0; d < 128; d++) acc += nd0[d] * w[d];
        qsh[a][el] = acc;
    }
    __syncthreads();

    for (int el = 0; el < 16; el++) {
        int e = e0 + el;
        float acc = 0.f;
#pragma unroll
        for (int a = 0; a < 8; a++)
            acc += qsh[a][el] * Wk_w[(size_t)((a << 7) + e) * 128 + t];
        d_M[(size_t)b * 16384 + e * 128 + t] = acc;
    }
    if (t < 16) {
        int e = e0 + t;
        float acc = 0.f;
#pragma unroll
        for (int a = 0; a < 8; a++) acc += qsh[a][t] * Wk_b[(a << 7) + e];
        d_c[b * 128 + e] = acc;
    }
}

// ---------------------------------------------------------------------------
// K2: qk = node @ M.T + c ; h/gelu -> d_e
// grid = B*nblk (16 rows), block = 256
// smem floats: Ms 128*132 | Wes 64*68 | Wbs 64*68 | nds 16*128 | e0s 16*64
//              | ems 16*64 | cs 128 | qks 16*128 = 31872
// ---------------------------------------------------------------------------
__global__ void k2_edgeattn(const float* __restrict__ node,
                            const float* __restrict__ edge,
                            const float* __restrict__ emb,
                            const float* __restrict__ Wew,
                            const float* __restrict__ Web,
                            int N, int nblk) {
    extern __shared__ float sm[];
    float* Ms  = sm;
    float* Wes = Ms + 128 * 132;
    float* Wbs = Wes + 64 * 68;
    float* nds = Wbs + 64 * 68;
    float* e0s = nds + 16 * 128;
    float* ems = e0s + 16 * 64;
    float* cs  = ems + 16 * 64;
    float* qks = cs + 128;

    int b  = blockIdx.x / nblk;
    int m0 = (blockIdx.x % nblk) * 16;
    int t  = threadIdx.x;
    int NM = N - 1;

    {
        const float4* src = (const float4*)(d_M + (size_t)b * 16384);
        for (int q = t; q < 4096; q += 256) {
            int e = q >> 5, d4 = q & 31;
            *(float4*)&Ms[e * 132 + 4 * d4] = src[q];
        }
    }
    for (int q = t; q < 1024; q += 256) {
        int j = q >> 4, d4 = q & 15;
        *(float4*)&Wes[j * 68 + 4 * d4] = ((const float4*)Wew)[q];
        *(float4*)&Wbs[j * 68 + 4 * d4] = ((const float4*)Web)[q];
    }
    if (t < 128) cs[t] = d_c[b * 128 + t];
    for (int q = t; q < 512; q += 256) {
        int r = q >> 5, d4 = q & 31;
        int m = m0 + r;
        float4 v = make_float4(0.f, 0.f, 0.f, 0.f);
        if (m < NM) v = *(const float4*)&node[((size_t)b * N + m + 1) * 128 + 4 * d4];
        *(float4*)&nds[r * 128 + 4 * d4] = v;
    }
    {
        int q = t;  // 16*64/4 = 256 exactly
        int r = q >> 4, d4 = q & 15;
        int m = m0 + r;
        float4 ve = make_float4(0.f, 0.f, 0.f, 0.f), vm = ve;
        if (m < NM) {
            size_t base = ((size_t)b * N * N + (size_t)(m + 1)) * 64 + 4 * d4;
            ve = *(const float4*)&edge[base];
            vm = *(const float4*)&emb[base];
        }
        *(float4*)&e0s[r * 64 + 4 * d4] = ve;
        *(float4*)&ems[r * 64 + 4 * d4] = vm;
    }
    __syncthreads();

    // qk: thread = (cp: cols cp, cp+64) x (rq: rows 4rq..4rq+3)
    {
        int cp = t & 63, rq = t >> 6;
        float a0[4] = {0.f, 0.f, 0.f, 0.f}, a1[4] = {0.f, 0.f, 0.f, 0.f};
        const float* m0p = Ms + cp * 132;
        const float* m1p = Ms + (cp + 64) * 132;
        const float* nb  = nds + rq * 4 * 128;
#pragma unroll 8
        for (int d4 = 0; d4 < 32; d4++) {
            float4 ma = *(const float4*)&m0p[4 * d4];
            float4 mb = *(const float4*)&m1p[4 * d4];
#pragma unroll
            for (int r = 0; r < 4; r++) {
                float4 n4 = *(const float4*)&nb[r * 128 + 4 * d4];
                a0[r] += dot4(ma, n4);
                a1[r] += dot4(mb, n4);
            }
        }
        float c0 = cs[cp], c1 = cs[cp + 64];
#pragma unroll
        for (int r = 0; r < 4; r++) {
            qks[(rq * 4 + r) * 128 + cp]      = a0[r] + c0;
            qks[(rq * 4 + r) * 128 + cp + 64] = a1[r] + c1;
        }
    }
    __syncthreads();

    // edge projections + gelu
    {
        int j = t & 63, rg = t >> 6;
        float ew[4] = {0.f, 0.f, 0.f, 0.f}, eb[4] = {0.f, 0.f, 0.f, 0.f};
        const float* wrow = Wes + j * 68;
        const float* brow = Wbs + j * 68;
#pragma unroll 8
        for (int d4 = 0; d4 < 16; d4++) {
            float4 w4 = *(const float4*)&wrow[4 * d4];
            float4 b4 = *(const float4*)&brow[4 * d4];
#pragma unroll
            for (int r = 0; r < 4; r++) {
                float4 x4 = *(const float4*)&e0s[(rg * 4 + r) * 64 + 4 * d4];
                ew[r] += dot4(w4, x4);
                eb[r] += dot4(b4, x4);
            }
        }
#pragma unroll
        for (int r = 0; r < 4; r++) {
            int rr = rg * 4 + r;
            int m = m0 + rr;
            if (m < NM) {
                float x = rhof(qks[rr * 128 + j] * ew[r]) + eb[r]
                        + qks[rr * 128 + 64 + j] + ems[rr * 64 + j];
                d_e[((size_t)b * NM + m) * 64 + j] = geluf(x);
            }
        }
    }
}

// ---------------------------------------------------------------------------
// K3: logits = e@Wa.T ; etr = e@et_w.T + b ; ntr = node@nt_w.T + b
// grid = B*nblk, block = 256
// smem: Was 128*68 | ews 128*68 | nts 128*132 | er 16*64 | ndr 16*128 = 37376
// ---------------------------------------------------------------------------
__global__ void k3_proj(const float* __restrict__ node,
                        const float* __restrict__ Wa,
                        const float* __restrict__ nt_w, const float* __restrict__ nt_b,
                        const float* __restrict__ et_w, const float* __restrict__ et_b,
                        int N, int nblk) {
    extern __shared__ float sm[];
    float* Was = sm;
    float* ews = Was + 128 * 68;
    float* nts = ews + 128 * 68;
    float* er  = nts + 128 * 132;
    float* ndr = er + 16 * 64;

    int b  = blockIdx.x / nblk;
    int m0 = (blockIdx.x % nblk) * 16;
    int t  = threadIdx.x;
    int NM = N - 1;

    for (int q = t; q < 2048; q += 256) {
        int i = q >> 4, d4 = q & 15;
        *(float4*)&Was[i * 68 + 4 * d4] = ((const float4*)Wa)[q];
        *(float4*)&ews[i * 68 + 4 * d4] = ((const float4*)et_w)[q];
    }
    for (int q = t; q < 4096; q += 256) {
        int i = q >> 5, d4 = q & 31;
        *(float4*)&nts[i * 132 + 4 * d4] = ((const float4*)nt_w)[q];
    }
    {
        int q = t;  // 16*64/4 = 256
        int r = q >> 4, d4 = q & 15;
        int m = m0 + r;
        float4 v = make_float4(0.f, 0.f, 0.f, 0.f);
        if (m < NM) v = *(const float4*)&d_e[((size_t)b * NM + m) * 64 + 4 * d4];
        *(float4*)&er[r * 64 + 4 * d4] = v;
    }
    for (int q = t; q < 512; q += 256) {
        int r = q >> 5, d4 = q & 31;
        int m = m0 + r;
        float4 v = make_float4(0.f, 0.f, 0.f, 0.f);
        if (m < NM) v = *(const float4*)&node[((size_t)b * N + m + 1) * 128 + 4 * d4];
        *(float4*)&ndr[r * 128 + 4 * d4] = v;
    }
    __syncthreads();

    int cp = t & 63, rq = t >> 6;
    float aa0[4] = {0,0,0,0}, aa1[4] = {0,0,0,0};
    float ae0[4] = {0,0,0,0}, ae1[4] = {0,0,0,0};
    float an0[4] = {0,0,0,0}, an1[4] = {0,0,0,0};

    const float* wa0 = Was + cp * 68;
    const float* wa1 = Was + (cp + 64) * 68;
    const float* we0 = ews + cp * 68;
    const float* we1 = ews + (cp + 64) * 68;
#pragma unroll 4
    for (int d4 = 0; d4 < 16; d4++) {
        float4 a4 = *(const float4*)&wa0[4 * d4];
        float4 b4 = *(const float4*)&wa1[4 * d4];
        float4 c4 = *(const float4*)&we0[4 * d4];
        float4 e4 = *(const float4*)&we1[4 * d4];
#pragma unroll
        for (int r = 0; r < 4; r++) {
            float4 x4 = *(const float4*)&er[(rq * 4 + r) * 64 + 4 * d4];
            aa0[r] += dot4(a4, x4);
            aa1[r] += dot4(b4, x4);
            ae0[r] += dot4(c4, x4);
            ae1[r] += dot4(e4, x4);
        }
    }
    const float* wn0 = nts + cp * 132;
    const float* wn1 = nts + (cp + 64) * 132;
#pragma unroll 8
    for (int d4 = 0; d4 < 32; d4++) {
        float4 a4 = *(const float4*)&wn0[4 * d4];
        float4 b4 = *(const float4*)&wn1[4 * d4];
#pragma unroll
        for (int r = 0; r < 4; r++) {
            float4 x4 = *(const float4*)&ndr[(rq * 4 + r) * 128 + 4 * d4];
            an0[r] += dot4(a4, x4);
            an1[r] += dot4(b4, x4);
        }
    }
    float be0 = et_b[cp], be1 = et_b[cp + 64];
    float bn0 = nt_b[cp], bn1 = nt_b[cp + 64];
#pragma unroll
    for (int r = 0; r < 4; r++) {
        int m = m0 + rq * 4 + r;
        if (m < NM) {
            size_t o = ((size_t)b * NM + m) * 128;
            d_logits[o + cp]      = aa0[r];
            d_logits[o + cp + 64] = aa1[r];
            d_etr[o + cp]         = ae0[r] + be0;
            d_etr[o + cp + 64]    = ae1[r] + be1;
            d_ntr[o + cp]         = an0[r] + bn0;
            d_ntr[o + cp + 64]    = an1[r] + bn1;
        }
    }
}

// ---------------------------------------------------------------------------
// K4a: partial online softmax. grid = B*nch (16 rows each), block = 256.
// ---------------------------------------------------------------------------
__global__ void k4a_part(int NM, int nch) {
    int b  = blockIdx.x / nch;
    int ch = blockIdx.x % nch;
    int m0 = ch * 16;
    int t  = threadIdx.x;
    int i  = t & 127, c = t >> 7;

    const float* base = d_logits + (size_t)b * NM * 128;
    float v[8];
#pragma unroll
    for (int r = 0; r < 8; r++) {
        int m = m0 + c * 8 + r;
        v[r] = (m < NM) ? base[(size_t)m * 128 + i] : -3.4e38f;
    }
    float mx = v[0];
#pragma unroll
    for (int r = 1; r < 8; r++) mx = fmaxf(mx, v[r]);
    float s = 0.f;
#pragma unroll
    for (int r = 0; r < 8; r++) s += expf(v[r] - mx);

    __shared__ float sm_m[256], sm_s[256];
    sm_m[t] = mx; sm_s[t] = s;
    __syncthreads();
    if (c == 0) {
        float m2 = sm_m[128 + i], s2 = sm_s[128 + i];
        float nm = fmaxf(mx, m2);
        float ns = s * expf(mx - nm) + s2 * expf(m2 - nm);
        d_pm[(b * nch + ch) * 128 + i] = nm;
        d_ps[(b * nch + ch) * 128 + i] = ns;
    }
}

// K4b: combine partials. grid = B, block = 128.
__global__ void k4b_comb(int nch) {
    int b = blockIdx.x, i = threadIdx.x;
    float m = -3.4e38f;
    for (int ch = 0; ch < nch; ch++) m = fmaxf(m, d_pm[(b * nch + ch) * 128 + i]);
    float s = 0.f;
    for (int ch = 0; ch < nch; ch++)
        s += d_ps[(b * nch + ch) * 128 + i] * expf(d_pm[(b * nch + ch) * 128 + i] - m);
    d_mx[b * 128 + i]  = m;
    d_inv[b * 128 + i] = 1.f / s;
}

// ---------------------------------------------------------------------------
// K5a: alpha = exp(logit-mx)*inv; v = [etr*a | ntr*a]; g = gelu(v@h1_w.T+b);
//      store et_p. grid = B*nblk, block = 256.
// smem: h1s 128*260 | v 16*260 | als 16*128 = 39488 floats
// ---------------------------------------------------------------------------
__global__ void k5a_h1(const float* __restrict__ h1_w, const float* __restrict__ h1_b,
                       float* __restrict__ out_et, int N, int nblk) {
    extern __shared__ float sm[];
    float* h1s = sm;
    float* v   = h1s + 128 * 260;
    float* als = v + 16 * 260;

    int b  = blockIdx.x / nblk;
    int m0 = (blockIdx.x % nblk) * 16;
    int t  = threadIdx.x;
    int NM = N - 1;

    for (int q = t; q < 8192; q += 256) {
        int i = q >> 6, d4 = q & 63;
        *(float4*)&h1s[i * 260 + 4 * d4] = ((const float4*)h1_w)[q];
    }
    for (int q = t; q < 2048; q += 256) {
        int r = q >> 7, i = q & 127;
        int m = m0 + r;
        float a = 0.f;
        if (m < NM)
            a = expf(d_logits[((size_t)b * NM + m) * 128 + i] - d_mx[b * 128 + i])
              * d_inv[b * 128 + i];
        als[q] = a;
    }
    __syncthreads();
    for (int q = t; q < 4096; q += 256) {
        int r = q >> 8, d = q & 255;
        int dd = d & 127;
        int m = m0 + r;
        float val = 0.f;
        if (m < NM) {
            size_t o = ((size_t)b * NM + m) * 128 + dd;
            val = ((d < 128) ? d_etr[o] : d_ntr[o]) * als[r * 128 + dd];
        }
        v[r * 260 + d] = val;
    }
    __syncthreads();

    // et_p store (coalesced-ish along m)
    {
        int mr = t & 15, ig = t >> 4;
        int m = m0 + mr;
        if (m < NM) {
#pragma unroll
            for (int ii = 0; ii < 8; ii++) {
                int i = ig * 8 + ii;
                out_et[((size_t)b * 128 + i) * NM + m] = v[mr * 260 + i];
            }
        }
    }

    int cp = t & 63, rq = t >> 6;
    float a0[4] = {0,0,0,0}, a1[4] = {0,0,0,0};
    const float* w0p = h1s + cp * 260;
    const float* w1p = h1s + (cp + 64) * 260;
#pragma unroll 8
    for (int d4 = 0; d4 < 64; d4++) {
        float4 w0 = *(const float4*)&w0p[4 * d4];
        float4 w1 = *(const float4*)&w1p[4 * d4];
#pragma unroll
        for (int r = 0; r < 4; r++) {
            float4 x4 = *(const float4*)&v[(rq * 4 + r) * 260 + 4 * d4];
            a0[r] += dot4(w0, x4);
            a1[r] += dot4(w1, x4);
        }
    }
    float b0 = h1_b[cp], b1 = h1_b[cp + 64];
#pragma unroll
    for (int r = 0; r < 4; r++) {
        int m = m0 + rq * 4 + r;
        if (m < NM) {
            size_t o = ((size_t)b * NM + m) * 128;
            d_g[o + cp]      = geluf(a0[r] + b0);
            d_g[o + cp + 64] = geluf(a1[r] + b1);
        }
    }
}

// ---------------------------------------------------------------------------
// K5b: tmp = g @ h2_w.T + b ; store tmp_p transposed. grid = B*nblk, block 256
// smem: h2s 128*132 | gr 16*128 | qo 128*17 = 21120 floats
// ---------------------------------------------------------------------------
__global__ void k5b_h2(const float* __restrict__ h2_w, const float* __restrict__ h2_b,
                       float* __restrict__ out_tmp, int N, int nblk) {
    extern __shared__ float sm[];
    float* h2s = sm;
    float* gr  = h2s + 128 * 132;
    float* qo  = gr + 16 * 128;

    int b  = blockIdx.x / nblk;
    int m0 = (blockIdx.x % nblk) * 16;
    int t  = threadIdx.x;
    int NM = N - 1;

    for (int q = t; q < 4096; q += 256) {
        int i = q >> 5, d4 = q & 31;
        *(float4*)&h2s[i * 132 + 4 * d4] = ((const float4*)h2_w)[q];
    }
    for (int q = t; q < 512; q += 256) {
        int r = q >> 5, d4 = q & 31;
        int m = m0 + r;
        float4 vv = make_float4(0.f, 0.f, 0.f, 0.f);
        if (m < NM) vv = *(const float4*)&d_g[((size_t)b * NM + m) * 128 + 4 * d4];
        *(float4*)&gr[r * 128 + 4 * d4] = vv;
    }
    __syncthreads();

    int cp = t & 63, rq = t >> 6;
    float a0[4] = {0,0,0,0}, a1[4] = {0,0,0,0};
    const float* w0p = h2s + cp * 132;
    const float* w1p = h2s + (cp + 64) * 132;
#pragma unroll 8
    for (int d4 = 0; d4 < 32; d4++) {
        float4 w0 = *(const float4*)&w0p[4 * d4];
        float4 w1 = *(const float4*)&w1p[4 * d4];
#pragma unroll
        for (int r = 0; r < 4; r++) {
            float4 x4 = *(const float4*)&gr[(rq * 4 + r) * 128 + 4 * d4];
            a0[r] += dot4(w0, x4);
            a1[r] += dot4(w1, x4);
        }
    }
    float b0 = h2_b[cp], b1 = h2_b[cp + 64];
#pragma unroll
    for (int r = 0; r < 4; r++) {
        int mr = rq * 4 + r;
        qo[cp * 17 + mr]        = a0[r] + b0;
        qo[(cp + 64) * 17 + mr] = a1[r] + b1;
    }
    __syncthreads();

    {
        int mr = t & 15, ig = t >> 4;
        int m = m0 + mr;
        if (m < NM) {
#pragma unroll
            for (int ii = 0; ii < 8; ii++) {
                int i = ig * 8 + ii;
                out_tmp[((size_t)b * 128 + i) * NM + m] = qo[i * 17 + mr];
            }
        }
    }
}

// ---------------------------------------------------------------------------
// K6: node_out[b,i] = scaler * sum_m tmp_p[b,i,m]
// ---------------------------------------------------------------------------
__global__ void k6_rowsum(const float* __restrict__ tmp_p, float* __restrict__ out_node,
                          int NM, float scaler) {
    int bi = blockIdx.x;
    const float* row = tmp_p + (size_t)bi * NM;
    float s = 0.f;
    for (int m = threadIdx.x; m < NM; m += 128) s += row[m];
#pragma unroll
    for (int o = 16; o > 0; o >>= 1) s += __shfl_down_sync(0xffffffffu, s, o);
    __shared__ float red[4];
    if ((threadIdx.x & 31) == 0) red[threadIdx.x >> 5] = s;
    __syncthreads();
    if (threadIdx.x == 0)
        out_node[bi] = (red[0] + red[1] + red[2] + red[3]) * scaler;
}

// ---------------------------------------------------------------------------
extern "C" void kernel_launch(void* const* d_in, const int* in_sizes, int n_in,
                              void* d_out, int out_size) {
    const float* node = (const float*)d_in[0];
    const float* edge = (const float*)d_in[1];
    const float* emb  = (const float*)d_in[2];
    const float* Wq_w = (const float*)d_in[3];
    const float* Wq_b = (const float*)d_in[4];
    const float* Wk_w = (const float*)d_in[5];
    const float* Wk_b = (const float*)d_in[6];
    const float* Wew  = (const float*)d_in[7];
    const float* Web  = (const float*)d_in[8];
    const float* Wa   = (const float*)d_in[9];
    const float* nt_w = (const float*)d_in[10];
    const float* nt_b = (const float*)d_in[11];
    const float* et_w = (const float*)d_in[12];
    const float* et_b = (const float*)d_in[13];
    const float* h1_w = (const float*)d_in[14];
    const float* h1_b = (const float*)d_in[15];
    const float* h2_w = (const float*)d_in[16];
    const float* h2_b = (const float*)d_in[17];

    long n_node = in_sizes[0];
    long n_edge = in_sizes[1];
    int N = (int)((2L * n_edge) / n_node);   // 512
    int B = (int)(n_node / ((long)N * 128)); // 4
    int NM = N - 1;
    int nblk = (NM + 15) / 16;               // 32

    float* out      = (float*)d_out;
    float* out_node = out;
    float* out_tmp  = out + (size_t)B * 128;
    float* out_et   = out_tmp + (size_t)B * 128 * NM;

    const int SM2  = 31872 * 4;
    const int SM3  = 37376 * 4;
    const int SM5A = 39488 * 4;
    const int SM5B = 21120 * 4;

    cudaFuncSetAttribute(k2_edgeattn, cudaFuncAttributeMaxDynamicSharedMemorySize, SM2);
    cudaFuncSetAttribute(k3_proj,     cudaFuncAttributeMaxDynamicSharedMemorySize, SM3);
    cudaFuncSetAttribute(k5a_h1,      cudaFuncAttributeMaxDynamicSharedMemorySize, SM5A);
    cudaFuncSetAttribute(k5b_h2,      cudaFuncAttributeMaxDynamicSharedMemorySize, SM5B);

    k1_fold<<<B * 8, 128>>>(node, Wq_w, Wq_b, Wk_w, Wk_b, N);
    k2_edgeattn<<<B * nblk, 256, SM2>>>(node, edge, emb, Wew, Web, N, nblk);
    k3_proj<<<B * nblk, 256, SM3>>>(node, Wa, nt_w, nt_b, et_w, et_b, N, nblk);
    k4a_part<<<B * nblk, 256>>>(NM, nblk);
    k4b_comb<<<B, 128>>>(nblk);
    k5a_h1<<<B * nblk, 256, SM5A>>>(h1_w, h1_b, out_et, N, nblk);
    k5b_h2<<<B * nblk, 256, SM5B>>>(h2_w, h2_b, out_tmp, N, nblk);

    float scaler = 2.0f / sqrtf(128.0f);
    k6_rowsum<<<B * 128, 128>>>(out_tmp, out_node, NM, scaler);
}

// round 3
// speedup vs baseline: 2.7648x; 1.4336x over previous
#include <cuda_runtime.h>
#include <math.h>

// Fixed problem dims (B=4, N=512, C=128, ED=64, ATT=8, IN=128)
#define MAXB 4
#define MAXNM 511
#define MAXCH 32

// ---------------- scratch (device globals) ----------------
__device__ float d_M[MAXB * 128 * 128];
__device__ float d_c[MAXB * 128];
__device__ float d_e[MAXB * MAXNM * 64];
__device__ float d_logits[MAXB * MAXNM * 128];
__device__ float d_etr[MAXB * MAXNM * 128];
__device__ float d_ntr[MAXB * MAXNM * 128];
__device__ float d_g[MAXB * MAXNM * 128];
__device__ float d_pm[MAXB * MAXCH * 128];
__device__ float d_ps[MAXB * MAXCH * 128];

__device__ __forceinline__ float geluf(float x) {
    return 0.5f * x * (1.0f + erff(x * 0.7071067811865476f));
}
__device__ __forceinline__ float rhof(float x) {
    return copysignf(sqrtf(fabsf(x)), x);
}
__device__ __forceinline__ float dot4(float4 a, float4 b) {
    return a.x * b.x + a.y * b.y + a.z * b.z + a.w * b.w;
}

// ---------------------------------------------------------------------------
// K1: fold q into M[b,e,d], c[b,e]; zero out_node
// grid = B*8, block = 128
// ---------------------------------------------------------------------------
__global__ void k1_fold(const float* __restrict__ node,
                        const float* __restrict__ Wq_w, const float* __restrict__ Wq_b,
                        const float* __restrict__ Wk_w, const float* __restrict__ Wk_b,
                        float* __restrict__ out_node, int B, int N) {
    int b = blockIdx.x >> 3;
    int s = blockIdx.x & 7;
    int e0 = s * 16;
    int t = threadIdx.x;

    if (blockIdx.x < B) out_node[blockIdx.x * 128 + t] = 0.f;

    __shared__ float nd0[128];
    __shared__ float qsh[8][16];

    nd0[t] = node[(size_t)b * N * 128 + t];
    __syncthreads();

    {
        int a = t >> 4, el = t & 15;
        int row = (a << 7) + e0 + el;
        const float* w = Wq_w + (size_t)row * 128;
        float acc = Wq_b[row];
#pragma unroll 4
        for (int d = 0; d < 128; d++) acc += nd0[d] * w[d];
        qsh[a][el] = acc;
    }
    __syncthreads();

    for (int el = 0; el < 16; el++) {
        int e = e0 + el;
        float acc = 0.f;
#pragma unroll
        for (int a = 0; a < 8; a++)
            acc += qsh[a][el] * Wk_w[(size_t)((a << 7) + e) * 128 + t];
        d_M[(size_t)b * 16384 + e * 128 + t] = acc;
    }
    if (t < 16) {
        int e = e0 + t;
        float acc = 0.f;
#pragma unroll
        for (int a = 0; a < 8; a++) acc += qsh[a][t] * Wk_b[(a << 7) + e];
        d_c[b * 128 + e] = acc;
    }
}

// ---------------------------------------------------------------------------
// K2: qk = node @ M.T + c (k-split across 2 groups); gelu edge stage -> d_e
// grid = B*nblk, block = 512
// smem fl: Ms 16896 | Wes 4352 | Wbs 4352 | nds 2048 | e0s 1024 | ems 1024
//          | cs 128 | qks 2048 | pbuf 2048 = 33920
// ---------------------------------------------------------------------------
__global__ void __launch_bounds__(512)
k2_edgeattn(const float* __restrict__ node,
            const float* __restrict__ edge,
            const float* __restrict__ emb,
            const float* __restrict__ Wew,
            const float* __restrict__ Web,
            int N, int nblk) {
    extern __shared__ float sm[];
    float* Ms   = sm;
    float* Wes  = Ms + 16896;
    float* Wbs  = Wes + 4352;
    float* nds  = Wbs + 4352;
    float* e0s  = nds + 2048;
    float* ems  = e0s + 1024;
    float* cs   = ems + 1024;
    float* qks  = cs + 128;
    float* pbuf = qks + 2048;

    int b  = blockIdx.x / nblk;
    int m0 = (blockIdx.x % nblk) * 16;
    int t  = threadIdx.x;
    int NM = N - 1;

    {
        const float4* src = (const float4*)(d_M + (size_t)b * 16384);
#pragma unroll
        for (int q = t; q < 4096; q += 512) {
            int e = q >> 5, d4 = q & 31;
            *(float4*)&Ms[e * 132 + 4 * d4] = src[q];
        }
    }
#pragma unroll
    for (int q = t; q < 1024; q += 512) {
        int j = q >> 4, d4 = q & 15;
        *(float4*)&Wes[j * 68 + 4 * d4] = ((const float4*)Wew)[q];
        *(float4*)&Wbs[j * 68 + 4 * d4] = ((const float4*)Web)[q];
    }
    if (t < 128) cs[t] = d_c[b * 128 + t];
    {
        int r = t >> 5, d4 = t & 31;
        int m = m0 + r;
        float4 v = make_float4(0.f, 0.f, 0.f, 0.f);
        if (m < NM) v = *(const float4*)&node[((size_t)b * N + m + 1) * 128 + 4 * d4];
        *(float4*)&nds[r * 128 + 4 * d4] = v;
    }
    {
        int q = t & 255;
        int r = q >> 4, d4 = q & 15;
        int m = m0 + r;
        float4 v = make_float4(0.f, 0.f, 0.f, 0.f);
        if (m < NM) {
            size_t base = ((size_t)b * N * N + (size_t)(m + 1)) * 64 + 4 * d4;
            v = (t < 256) ? *(const float4*)&edge[base] : *(const float4*)&emb[base];
        }
        if (t < 256) *(float4*)&e0s[r * 64 + 4 * d4] = v;
        else         *(float4*)&ems[r * 64 + 4 * d4] = v;
    }
    __syncthreads();

    // phase A: qk, k-split (each group handles 64 of 128 k)
    {
        int kh = t >> 8, tt = t & 255;
        int cp = tt & 63, rq = tt >> 6;
        float a0[4] = {0,0,0,0}, a1[4] = {0,0,0,0};
        const float* m0p = Ms + cp * 132 + kh * 64;
        const float* m1p = Ms + (cp + 64) * 132 + kh * 64;
        const float* nb  = nds + rq * 4 * 128 + kh * 64;
#pragma unroll
        for (int d4 = 0; d4 < 16; d4++) {
            float4 ma = *(const float4*)&m0p[4 * d4];
            float4 mb = *(const float4*)&m1p[4 * d4];
#pragma unroll
            for (int r = 0; r < 4; r++) {
                float4 n4 = *(const float4*)&nb[r * 128 + 4 * d4];
                a0[r] += dot4(ma, n4);
                a1[r] += dot4(mb, n4);
            }
        }
        if (kh == 1) {
#pragma unroll
            for (int r = 0; r < 4; r++) {
                pbuf[(rq * 4 + r) * 128 + cp]      = a0[r];
                pbuf[(rq * 4 + r) * 128 + cp + 64] = a1[r];
            }
        }
        __syncthreads();
        if (kh == 0) {
            float c0 = cs[cp], c1 = cs[cp + 64];
#pragma unroll
            for (int r = 0; r < 4; r++) {
                int rw = rq * 4 + r;
                qks[rw * 128 + cp]      = a0[r] + pbuf[rw * 128 + cp] + c0;
                qks[rw * 128 + cp + 64] = a1[r] + pbuf[rw * 128 + cp + 64] + c1;
            }
        }
        __syncthreads();
    }

    // phase B: edge projections + gelu, 512 threads, 2 rows each
    {
        int j = t & 63, rg = t >> 6;  // rg 0..7
        float ew[2] = {0.f, 0.f}, eb[2] = {0.f, 0.f};
        const float* wrow = Wes + j * 68;
        const float* brow = Wbs + j * 68;
#pragma unroll
        for (int d4 = 0; d4 < 16; d4++) {
            float4 w4 = *(const float4*)&wrow[4 * d4];
            float4 b4 = *(const float4*)&brow[4 * d4];
#pragma unroll
            for (int r = 0; r < 2; r++) {
                float4 x4 = *(const float4*)&e0s[(rg * 2 + r) * 64 + 4 * d4];
                ew[r] += dot4(w4, x4);
                eb[r] += dot4(b4, x4);
            }
        }
#pragma unroll
        for (int r = 0; r < 2; r++) {
            int rr = rg * 2 + r;
            int m = m0 + rr;
            if (m < NM) {
                float x = rhof(qks[rr * 128 + j] * ew[r]) + eb[r]
                        + qks[rr * 128 + 64 + j] + ems[rr * 64 + j];
                d_e[((size_t)b * NM + m) * 64 + j] = geluf(x);
            }
        }
    }
}

// ---------------------------------------------------------------------------
// K3: group A (t<256): logits = e@Wa.T, etr = e@et_w.T + b  + partial softmax
//     group B (t>=256): ntr = node@nt_w.T + b
// grid = B*nblk, block = 512
// smem fl: Was 8704 | ews 8704 | nts 16896 | er 1024 | ndr 2048
//          | redm 512 | reds 512 = 38400
// ---------------------------------------------------------------------------
__global__ void __launch_bounds__(512)
k3_proj(const float* __restrict__ node,
        const float* __restrict__ Wa,
        const float* __restrict__ nt_w, const float* __restrict__ nt_b,
        const float* __restrict__ et_w, const float* __restrict__ et_b,
        int N, int nblk) {
    extern __shared__ float sm[];
    float* Was  = sm;
    float* ews  = Was + 8704;
    float* nts  = ews + 8704;
    float* er   = nts + 16896;
    float* ndr  = er + 1024;
    float* redm = ndr + 2048;
    float* reds = redm + 512;

    int b  = blockIdx.x / nblk;
    int ch = blockIdx.x % nblk;
    int m0 = ch * 16;
    int t  = threadIdx.x;
    int NM = N - 1;

#pragma unroll
    for (int q = t; q < 2048; q += 512) {
        int i = q >> 4, d4 = q & 15;
        *(float4*)&Was[i * 68 + 4 * d4] = ((const float4*)Wa)[q];
        *(float4*)&ews[i * 68 + 4 * d4] = ((const float4*)et_w)[q];
    }
#pragma unroll
    for (int q = t; q < 4096; q += 512) {
        int i = q >> 5, d4 = q & 31;
        *(float4*)&nts[i * 132 + 4 * d4] = ((const float4*)nt_w)[q];
    }
    if (t < 256) {
        int r = t >> 4, d4 = t & 15;
        int m = m0 + r;
        float4 v = make_float4(0.f, 0.f, 0.f, 0.f);
        if (m < NM) v = *(const float4*)&d_e[((size_t)b * NM + m) * 64 + 4 * d4];
        *(float4*)&er[r * 64 + 4 * d4] = v;
    }
    {
        int r = t >> 5, d4 = t & 31;
        int m = m0 + r;
        float4 v = make_float4(0.f, 0.f, 0.f, 0.f);
        if (m < NM) v = *(const float4*)&node[((size_t)b * N + m + 1) * 128 + 4 * d4];
        *(float4*)&ndr[r * 128 + 4 * d4] = v;
    }
    __syncthreads();

    if (t < 256) {
        // group A: logits + etr, k=64
        int cp = t & 63, rq = t >> 6;
        float aa0[4] = {0,0,0,0}, aa1[4] = {0,0,0,0};
        float ae0[4] = {0,0,0,0}, ae1[4] = {0,0,0,0};
        const float* wa0 = Was + cp * 68;
        const float* wa1 = Was + (cp + 64) * 68;
        const float* we0 = ews + cp * 68;
        const float* we1 = ews + (cp + 64) * 68;
#pragma unroll
        for (int d4 = 0; d4 < 16; d4++) {
            float4 a4 = *(const float4*)&wa0[4 * d4];
            float4 b4 = *(const float4*)&wa1[4 * d4];
            float4 c4 = *(const float4*)&we0[4 * d4];
            float4 e4 = *(const float4*)&we1[4 * d4];
#pragma unroll
            for (int r = 0; r < 4; r++) {
                float4 x4 = *(const float4*)&er[(rq * 4 + r) * 64 + 4 * d4];
                aa0[r] += dot4(a4, x4);
                aa1[r] += dot4(b4, x4);
                ae0[r] += dot4(c4, x4);
                ae1[r] += dot4(e4, x4);
            }
        }
        float be0 = et_b[cp], be1 = et_b[cp + 64];
        float lm0 = -3.4e38f, lm1 = -3.4e38f;
#pragma unroll
        for (int r = 0; r < 4; r++) {
            int m = m0 + rq * 4 + r;
            if (m < NM) {
                size_t o = ((size_t)b * NM + m) * 128;
                d_logits[o + cp]      = aa0[r];
                d_logits[o + cp + 64] = aa1[r];
                d_etr[o + cp]         = ae0[r] + be0;
                d_etr[o + cp + 64]    = ae1[r] + be1;
                lm0 = fmaxf(lm0, aa0[r]);
                lm1 = fmaxf(lm1, aa1[r]);
            }
        }
        float ls0 = 0.f, ls1 = 0.f;
#pragma unroll
        for (int r = 0; r < 4; r++) {
            int m = m0 + rq * 4 + r;
            if (m < NM) {
                ls0 += expf(aa0[r] - lm0);
                ls1 += expf(aa1[r] - lm1);
            }
        }
        redm[cp * 4 + rq]        = lm0;
        reds[cp * 4 + rq]        = ls0;
        redm[(cp + 64) * 4 + rq] = lm1;
        reds[(cp + 64) * 4 + rq] = ls1;
    } else {
        // group B: ntr, k=128
        int tt = t - 256;
        int cp = tt & 63, rq = tt >> 6;
        float an0[4] = {0,0,0,0}, an1[4] = {0,0,0,0};
        const float* wn0 = nts + cp * 132;
        const float* wn1 = nts + (cp + 64) * 132;
#pragma unroll 8
        for (int d4 = 0; d4 < 32; d4++) {
            float4 a4 = *(const float4*)&wn0[4 * d4];
            float4 b4 = *(const float4*)&wn1[4 * d4];
#pragma unroll
            for (int r = 0; r < 4; r++) {
                float4 x4 = *(const float4*)&ndr[(rq * 4 + r) * 128 + 4 * d4];
                an0[r] += dot4(a4, x4);
                an1[r] += dot4(b4, x4);
            }
        }
        float bn0 = nt_b[cp], bn1 = nt_b[cp + 64];
#pragma unroll
        for (int r = 0; r < 4; r++) {
            int m = m0 + rq * 4 + r;
            if (m < NM) {
                size_t o = ((size_t)b * NM + m) * 128;
                d_ntr[o + cp]      = an0[r] + bn0;
                d_ntr[o + cp + 64] = an1[r] + bn1;
            }
        }
    }
    __syncthreads();

    if (t < 128) {
        int i = t;
        float m = -3.4e38f;
#pragma unroll
        for (int g = 0; g < 4; g++) m = fmaxf(m, redm[i * 4 + g]);
        float s = 0.f;
#pragma unroll
        for (int g = 0; g < 4; g++) s += reds[i * 4 + g] * expf(redm[i * 4 + g] - m);
        d_pm[(b * nblk + ch) * 128 + i] = m;
        d_ps[(b * nblk + ch) * 128 + i] = s;
    }
}

// ---------------------------------------------------------------------------
// K5a: combine softmax partials; alpha; v = [etr*a | ntr*a]; g = gelu(v@h1_w.T+b)
//      (k-split); store et_p.
// grid = B*nblk, block = 512
// smem fl: h1s 33280 | v 4160 | als 2048 | pbuf 2048 | mxs 128 | invs 128
//          | redm 512 | reds 512 = 42816
// ---------------------------------------------------------------------------
__global__ void __launch_bounds__(512)
k5a_h1(const float* __restrict__ h1_w, const float* __restrict__ h1_b,
       float* __restrict__ out_et, int N, int nblk) {
    extern __shared__ float sm[];
    float* h1s  = sm;
    float* v    = h1s + 33280;
    float* als  = v + 4160;
    float* pbuf = als + 2048;
    float* mxs  = pbuf + 2048;
    float* invs = mxs + 128;
    float* redm = invs + 128;
    float* reds = redm + 512;

    int b  = blockIdx.x / nblk;
    int m0 = (blockIdx.x % nblk) * 16;
    int t  = threadIdx.x;
    int NM = N - 1;

#pragma unroll
    for (int q = t; q < 8192; q += 512) {
        int i = q >> 6, d4 = q & 63;
        *(float4*)&h1s[i * 260 + 4 * d4] = ((const float4*)h1_w)[q];
    }
    // softmax combine: online merge across 32 chunks
    {
        int i = t & 127, cg = t >> 7;  // cg 0..3
        float m = -3.4e38f, s = 0.f;
        for (int chh = cg; chh < nblk; chh += 4) {
            float pm = d_pm[(b * nblk + chh) * 128 + i];
            float ps = d_ps[(b * nblk + chh) * 128 + i];
            float nm = fmaxf(m, pm);
            s = s * expf(m - nm) + ps * expf(pm - nm);
            m = nm;
        }
        redm[i * 4 + cg] = m;
        reds[i * 4 + cg] = s;
    }
    __syncthreads();
    if (t < 128) {
        int i = t;
        float m = -3.4e38f;
#pragma unroll
        for (int g = 0; g < 4; g++) m = fmaxf(m, redm[i * 4 + g]);
        float s = 0.f;
#pragma unroll
        for (int g = 0; g < 4; g++) s += reds[i * 4 + g] * expf(redm[i * 4 + g] - m);
        mxs[i]  = m;
        invs[i] = 1.f / s;
    }
    __syncthreads();

#pragma unroll
    for (int q = t; q < 2048; q += 512) {
        int r = q >> 7, i = q & 127;
        int m = m0 + r;
        float a = 0.f;
        if (m < NM)
            a = expf(d_logits[((size_t)b * NM + m) * 128 + i] - mxs[i]) * invs[i];
        als[q] = a;
    }
    __syncthreads();
#pragma unroll
    for (int q = t; q < 4096; q += 512) {
        int r = q >> 8, d = q & 255;
        int dd = d & 127;
        int m = m0 + r;
        float val = 0.f;
        if (m < NM) {
            size_t o = ((size_t)b * NM + m) * 128 + dd;
            val = ((d < 128) ? d_etr[o] : d_ntr[o]) * als[r * 128 + dd];
        }
        v[r * 260 + d] = val;
    }
    __syncthreads();

    // et_p store
#pragma unroll
    for (int q = t; q < 2048; q += 512) {
        int i = q >> 4, mr = q & 15;
        int m = m0 + mr;
        if (m < NM) out_et[((size_t)b * 128 + i) * NM + m] = v[mr * 260 + i];
    }

    // h1 GEMM, k-split (k=256 -> 128 each)
    {
        int kh = t >> 8, tt = t & 255;
        int cp = tt & 63, rq = tt >> 6;
        float a0[4] = {0,0,0,0}, a1[4] = {0,0,0,0};
        const float* w0p = h1s + cp * 260 + kh * 128;
        const float* w1p = h1s + (cp + 64) * 260 + kh * 128;
        const float* vb  = v + rq * 4 * 260 + kh * 128;
#pragma unroll 8
        for (int d4 = 0; d4 < 32; d4++) {
            float4 w0 = *(const float4*)&w0p[4 * d4];
            float4 w1 = *(const float4*)&w1p[4 * d4];
#pragma unroll
            for (int r = 0; r < 4; r++) {
                float4 x4 = *(const float4*)&vb[r * 260 + 4 * d4];
                a0[r] += dot4(w0, x4);
                a1[r] += dot4(w1, x4);
            }
        }
        if (kh == 1) {
#pragma unroll
            for (int r = 0; r < 4; r++) {
                pbuf[(rq * 4 + r) * 128 + cp]      = a0[r];
                pbuf[(rq * 4 + r) * 128 + cp + 64] = a1[r];
            }
        }
        __syncthreads();
        if (kh == 0) {
            float b0 = h1_b[cp], b1 = h1_b[cp + 64];
#pragma unroll
            for (int r = 0; r < 4; r++) {
                int rw = rq * 4 + r;
                int m = m0 + rw;
                if (m < NM) {
                    size_t o = ((size_t)b * NM + m) * 128;
                    d_g[o + cp]      = geluf(a0[r] + pbuf[rw * 128 + cp] + b0);
                    d_g[o + cp + 64] = geluf(a1[r] + pbuf[rw * 128 + cp + 64] + b1);
                }
            }
        }
    }
}

// ---------------------------------------------------------------------------
// K5b: tmp = g @ h2_w.T + b (k-split); store tmp_p transposed; node_out atomic
// grid = B*nblk, block = 512
// smem fl: h2s 16896 | gr 2048 | qo 2176 | pbuf 2048 = 23168
// ---------------------------------------------------------------------------
__global__ void __launch_bounds__(512)
k5b_h2(const float* __restrict__ h2_w, const float* __restrict__ h2_b,
       float* __restrict__ out_tmp, float* __restrict__ out_node,
       int N, int nblk, float scaler) {
    extern __shared__ float sm[];
    float* h2s  = sm;
    float* gr   = h2s + 16896;
    float* qo   = gr + 2048;
    float* pbuf = qo + 2176;

    int b  = blockIdx.x / nblk;
    int m0 = (blockIdx.x % nblk) * 16;
    int t  = threadIdx.x;
    int NM = N - 1;

#pragma unroll
    for (int q = t; q < 4096; q += 512) {
        int i = q >> 5, d4 = q & 31;
        *(float4*)&h2s[i * 132 + 4 * d4] = ((const float4*)h2_w)[q];
    }
    {
        int r = t >> 5, d4 = t & 31;
        int m = m0 + r;
        float4 vv = make_float4(0.f, 0.f, 0.f, 0.f);
        if (m < NM) vv = *(const float4*)&d_g[((size_t)b * NM + m) * 128 + 4 * d4];
        *(float4*)&gr[r * 128 + 4 * d4] = vv;
    }
    __syncthreads();

    {
        int kh = t >> 8, tt = t & 255;
        int cp = tt & 63, rq = tt >> 6;
        float a0[4] = {0,0,0,0}, a1[4] = {0,0,0,0};
        const float* w0p = h2s + cp * 132 + kh * 64;
        const float* w1p = h2s + (cp + 64) * 132 + kh * 64;
        const float* gb  = gr + rq * 4 * 128 + kh * 64;
#pragma unroll
        for (int d4 = 0; d4 < 16; d4++) {
            float4 w0 = *(const float4*)&w0p[4 * d4];
            float4 w1 = *(const float4*)&w1p[4 * d4];
#pragma unroll
            for (int r = 0; r < 4; r++) {
                float4 x4 = *(const float4*)&gb[r * 128 + 4 * d4];
                a0[r] += dot4(w0, x4);
                a1[r] += dot4(w1, x4);
            }
        }
        if (kh == 1) {
#pragma unroll
            for (int r = 0; r < 4; r++) {
                pbuf[(rq * 4 + r) * 128 + cp]      = a0[r];
                pbuf[(rq * 4 + r) * 128 + cp + 64] = a1[r];
            }
        }
        __syncthreads();
        if (kh == 0) {
            float b0 = h2_b[cp], b1 = h2_b[cp + 64];
#pragma unroll
            for (int r = 0; r < 4; r++) {
                int rw = rq * 4 + r;
                int m = m0 + rw;
                float t0 = (m < NM) ? a0[r] + pbuf[rw * 128 + cp] + b0 : 0.f;
                float t1 = (m < NM) ? a1[r] + pbuf[rw * 128 + cp + 64] + b1 : 0.f;
                qo[cp * 17 + rw]        = t0;
                qo[(cp + 64) * 17 + rw] = t1;
            }
        }
        __syncthreads();
    }

    // transposed store
#pragma unroll
    for (int q = t; q < 2048; q += 512) {
        int i = q >> 4, mr = q & 15;
        int m = m0 + mr;
        if (m < NM) out_tmp[((size_t)b * 128 + i) * NM + m] = qo[i * 17 + mr];
    }
    // node_out partial
    if (t < 128) {
        int i = t;
        float s = 0.f;
#pragma unroll
        for (int mr = 0; mr < 16; mr++) s += qo[i * 17 + mr];
        atomicAdd(&out_node[b * 128 + i], s * scaler);
    }
}

// ---------------------------------------------------------------------------
extern "C" void kernel_launch(void* const* d_in, const int* in_sizes, int n_in,
                              void* d_out, int out_size) {
    const float* node = (const float*)d_in[0];
    const float* edge = (const float*)d_in[1];
    const float* emb  = (const float*)d_in[2];
    const float* Wq_w = (const float*)d_in[3];
    const float* Wq_b = (const float*)d_in[4];
    const float* Wk_w = (const float*)d_in[5];
    const float* Wk_b = (const float*)d_in[6];
    const float* Wew  = (const float*)d_in[7];
    const float* Web  = (const float*)d_in[8];
    const float* Wa   = (const float*)d_in[9];
    const float* nt_w = (const float*)d_in[10];
    const float* nt_b = (const float*)d_in[11];
    const float* et_w = (const float*)d_in[12];
    const float* et_b = (const float*)d_in[13];
    const float* h1_w = (const float*)d_in[14];
    const float* h1_b = (const float*)d_in[15];
    const float* h2_w = (const float*)d_in[16];
    const float* h2_b = (const float*)d_in[17];

    long n_node = in_sizes[0];
    long n_edge = in_sizes[1];
    int N = (int)((2L * n_edge) / n_node);   // 512
    int B = (int)(n_node / ((long)N * 128)); // 4
    int NM = N - 1;
    int nblk = (NM + 15) / 16;               // 32

    float* out      = (float*)d_out;
    float* out_node = out;
    float* out_tmp  = out + (size_t)B * 128;
    float* out_et   = out_tmp + (size_t)B * 128 * NM;

    const int SM2  = 33920 * 4;
    const int SM3  = 38400 * 4;
    const int SM5A = 42816 * 4;
    const int SM5B = 23168 * 4;

    cudaFuncSetAttribute(k2_edgeattn, cudaFuncAttributeMaxDynamicSharedMemorySize, SM2);
    cudaFuncSetAttribute(k3_proj,     cudaFuncAttributeMaxDynamicSharedMemorySize, SM3);
    cudaFuncSetAttribute(k5a_h1,      cudaFuncAttributeMaxDynamicSharedMemorySize, SM5A);
    cudaFuncSetAttribute(k5b_h2,      cudaFuncAttributeMaxDynamicSharedMemorySize, SM5B);

    float scaler = 2.0f / sqrtf(128.0f);

    k1_fold<<<B * 8, 128>>>(node, Wq_w, Wq_b, Wk_w, Wk_b, out_node, B, N);
    k2_edgeattn<<<B * nblk, 512, SM2>>>(node, edge, emb, Wew, Web, N, nblk);
    k3_proj<<<B * nblk, 512, SM3>>>(node, Wa, nt_w, nt_b, et_w, et_b, N, nblk);
    k5a_h1<<<B * nblk, 512, SM5A>>>(h1_w, h1_b, out_et, N, nblk);
    k5b_h2<<<B * nblk, 512, SM5B>>>(h2_w, h2_b, out_tmp, out_node, N, nblk, scaler);
}

// round 4
// speedup vs baseline: 3.0541x; 1.1046x over previous
#include <cuda_runtime.h>
#include <math.h>

// Fixed problem dims (B=4, N=512, C=128, ED=64, ATT=8, IN=128)
#define MAXB 4
#define MAXNM 511
#define MAXCH 32

typedef unsigned long long u64;

// ---------------- scratch (device globals) ----------------
__device__ float d_M[MAXB * 128 * 128];
__device__ float d_c[MAXB * 128];
__device__ float d_logits[MAXB * MAXNM * 128];
__device__ float d_etr[MAXB * MAXNM * 128];
__device__ float d_ntr[MAXB * MAXNM * 128];
__device__ float d_pm[MAXB * MAXCH * 128];
__device__ float d_ps[MAXB * MAXCH * 128];

__device__ __forceinline__ float geluf(float x) {
    return 0.5f * x * (1.0f + erff(x * 0.7071067811865476f));
}
__device__ __forceinline__ float rhof(float x) {
    return copysignf(sqrtf(fabsf(x)), x);
}
// packed f32x2 FMA: acc += a*b (two lanes)
__device__ __forceinline__ void ffma2(u64& acc, u64 a, u64 b) {
    asm("fma.rn.f32x2 %0, %1, %2, %0;" : "+l"(acc) : "l"(a), "l"(b));
}
__device__ __forceinline__ u64 lo2(const float4& v) { return *(const u64*)&v.x; }
__device__ __forceinline__ u64 hi2(const float4& v) { return *(const u64*)&v.z; }
__device__ __forceinline__ float red2(u64 v) {
    return __uint_as_float((unsigned)v) + __uint_as_float((unsigned)(v >> 32));
}

// ---------------------------------------------------------------------------
// K1: fold q into M[b,e,d], c[b,e]; zero out_node
// ---------------------------------------------------------------------------
__global__ void k1_fold(const float* __restrict__ node,
                        const float* __restrict__ Wq_w, const float* __restrict__ Wq_b,
                        const float* __restrict__ Wk_w, const float* __restrict__ Wk_b,
                        float* __restrict__ out_node, int B, int N) {
    int b = blockIdx.x >> 3;
    int s = blockIdx.x & 7;
    int e0 = s * 16;
    int t = threadIdx.x;

    if (blockIdx.x < B) out_node[blockIdx.x * 128 + t] = 0.f;

    __shared__ float nd0[128];
    __shared__ float qsh[8][16];

    nd0[t] = node[(size_t)b * N * 128 + t];
    __syncthreads();

    {
        int a = t >> 4, el = t & 15;
        int row = (a << 7) + e0 + el;
        const float* w = Wq_w + (size_t)row * 128;
        float acc = Wq_b[row];
#pragma unroll 4
        for (int d = 0; d < 128; d++) acc += nd0[d] * w[d];
        qsh[a][el] = acc;
    }
    __syncthreads();

    for (int el = 0; el < 16; el++) {
        int e = e0 + el;
        float acc = 0.f;
#pragma unroll
        for (int a = 0; a < 8; a++)
            acc += qsh[a][el] * Wk_w[(size_t)((a << 7) + e) * 128 + t];
        d_M[(size_t)b * 16384 + e * 128 + t] = acc;
    }
    if (t < 16) {
        int e = e0 + t;
        float acc = 0.f;
#pragma unroll
        for (int a = 0; a < 8; a++) acc += qsh[a][t] * Wk_b[(a << 7) + e];
        d_c[b * 128 + e] = acc;
    }
}

// ---------------------------------------------------------------------------
// K23: fused k2 (qk + edge gelu) and k3 (logits/etr/ntr + softmax partials)
// grid = B*nblk, block = 512
// smem floats (53440 total):
//   Ms 16896 (overlaid by nt_w after edge phase) | Wes 4352 | Wbs 4352 |
//   Was 8704 | ews 8704 | nds 2048 | e0s 1024 | ems 1024 | cs 128 |
//   qks 2048 | pbuf 2048 | er 1088 | redm 512 | reds 512
// ---------------------------------------------------------------------------
__global__ void __launch_bounds__(512)
k23(const float* __restrict__ node,
    const float* __restrict__ edge,
    const float* __restrict__ emb,
    const float* __restrict__ Wew,
    const float* __restrict__ Web,
    const float* __restrict__ Wa,
    const float* __restrict__ nt_w, const float* __restrict__ nt_b,
    const float* __restrict__ et_w, const float* __restrict__ et_b,
    int N, int nblk) {
    extern __shared__ float sm[];
    float* Ms   = sm;
    float* Wes  = Ms + 16896;
    float* Wbs  = Wes + 4352;
    float* Was  = Wbs + 4352;
    float* ews  = Was + 8704;
    float* nds  = ews + 8704;
    float* e0s  = nds + 2048;
    float* ems  = e0s + 1024;
    float* cs   = ems + 1024;
    float* qks  = cs + 128;
    float* pbuf = qks + 2048;
    float* er   = pbuf + 2048;
    float* redm = er + 1088;
    float* reds = redm + 512;

    int b  = blockIdx.x / nblk;
    int ch = blockIdx.x % nblk;
    int m0 = ch * 16;
    int t  = threadIdx.x;
    int NM = N - 1;

    // ---- phase 0: loads ----
    {
        const float4* src = (const float4*)(d_M + (size_t)b * 16384);
#pragma unroll
        for (int q = t; q < 4096; q += 512) {
            int e = q >> 5, d4 = q & 31;
            *(float4*)&Ms[e * 132 + 4 * d4] = src[q];
        }
    }
#pragma unroll
    for (int q = t; q < 1024; q += 512) {
        int j = q >> 4, d4 = q & 15;
        *(float4*)&Wes[j * 68 + 4 * d4] = ((const float4*)Wew)[q];
        *(float4*)&Wbs[j * 68 + 4 * d4] = ((const float4*)Web)[q];
    }
#pragma unroll
    for (int q = t; q < 2048; q += 512) {
        int i = q >> 4, d4 = q & 15;
        *(float4*)&Was[i * 68 + 4 * d4] = ((const float4*)Wa)[q];
        *(float4*)&ews[i * 68 + 4 * d4] = ((const float4*)et_w)[q];
    }
    if (t < 128) cs[t] = d_c[b * 128 + t];
    {
        int r = t >> 5, d4 = t & 31;
        int m = m0 + r;
        float4 v = make_float4(0.f, 0.f, 0.f, 0.f);
        if (m < NM) v = *(const float4*)&node[((size_t)b * N + m + 1) * 128 + 4 * d4];
        *(float4*)&nds[r * 128 + 4 * d4] = v;
    }
    {
        int q = t & 255;
        int r = q >> 4, d4 = q & 15;
        int m = m0 + r;
        float4 v = make_float4(0.f, 0.f, 0.f, 0.f);
        if (m < NM) {
            size_t base = ((size_t)b * N * N + (size_t)(m + 1)) * 64 + 4 * d4;
            v = (t < 256) ? *(const float4*)&edge[base] : *(const float4*)&emb[base];
        }
        if (t < 256) *(float4*)&e0s[r * 64 + 4 * d4] = v;
        else         *(float4*)&ems[r * 64 + 4 * d4] = v;
    }
    __syncthreads();

    // ---- phase A: qk (k-split 2, packed fma) ----
    {
        int kh = t >> 8, tt = t & 255;
        int cp = tt & 63, rq = tt >> 6;
        u64 a0[4] = {0,0,0,0}, a1[4] = {0,0,0,0};
        const float* m0p = Ms + cp * 132 + kh * 64;
        const float* m1p = Ms + (cp + 64) * 132 + kh * 64;
        const float* nb  = nds + rq * 4 * 128 + kh * 64;
#pragma unroll
        for (int d4 = 0; d4 < 16; d4++) {
            float4 ma = *(const float4*)&m0p[4 * d4];
            float4 mb = *(const float4*)&m1p[4 * d4];
            u64 mal = lo2(ma), mah = hi2(ma), mbl = lo2(mb), mbh = hi2(mb);
#pragma unroll
            for (int r = 0; r < 4; r++) {
                float4 n4 = *(const float4*)&nb[r * 128 + 4 * d4];
                u64 nl = lo2(n4), nh = hi2(n4);
                ffma2(a0[r], mal, nl); ffma2(a0[r], mah, nh);
                ffma2(a1[r], mbl, nl); ffma2(a1[r], mbh, nh);
            }
        }
        if (kh == 1) {
#pragma unroll
            for (int r = 0; r < 4; r++) {
                pbuf[(rq * 4 + r) * 128 + cp]      = red2(a0[r]);
                pbuf[(rq * 4 + r) * 128 + cp + 64] = red2(a1[r]);
            }
        }
        __syncthreads();
        if (kh == 0) {
            float c0 = cs[cp], c1 = cs[cp + 64];
#pragma unroll
            for (int r = 0; r < 4; r++) {
                int rw = rq * 4 + r;
                qks[rw * 128 + cp]      = red2(a0[r]) + pbuf[rw * 128 + cp] + c0;
                qks[rw * 128 + cp + 64] = red2(a1[r]) + pbuf[rw * 128 + cp + 64] + c1;
            }
        }
        __syncthreads();
    }

    // ---- phase B: edge projections + gelu -> er (smem) ----
    {
        int j = t & 63, rg = t >> 6;
        u64 ew2[2] = {0, 0}, eb2[2] = {0, 0};
        const float* wrow = Wes + j * 68;
        const float* brow = Wbs + j * 68;
#pragma unroll
        for (int d4 = 0; d4 < 16; d4++) {
            float4 w4 = *(const float4*)&wrow[4 * d4];
            float4 b4 = *(const float4*)&brow[4 * d4];
            u64 wl = lo2(w4), wh = hi2(w4), bl = lo2(b4), bh = hi2(b4);
#pragma unroll
            for (int r = 0; r < 2; r++) {
                float4 x4 = *(const float4*)&e0s[(rg * 2 + r) * 64 + 4 * d4];
                u64 xl = lo2(x4), xh = hi2(x4);
                ffma2(ew2[r], wl, xl); ffma2(ew2[r], wh, xh);
                ffma2(eb2[r], bl, xl); ffma2(eb2[r], bh, xh);
            }
        }
#pragma unroll
        for (int r = 0; r < 2; r++) {
            int rr = rg * 2 + r;
            int m = m0 + rr;
            float val = 0.f;
            if (m < NM) {
                float x = rhof(qks[rr * 128 + j] * red2(ew2[r])) + red2(eb2[r])
                        + qks[rr * 128 + 64 + j] + ems[rr * 64 + j];
                val = geluf(x);
            }
            er[rr * 68 + j] = val;
        }
    }
    __syncthreads();

    // ---- overlay nt_w into Ms region ----
#pragma unroll
    for (int q = t; q < 4096; q += 512) {
        int i = q >> 5, d4 = q & 31;
        *(float4*)&Ms[i * 132 + 4 * d4] = ((const float4*)nt_w)[q];
    }
    __syncthreads();

    // ---- phase C: k3 ----
    if (t < 256) {
        // group A: logits (Wa) + etr (et_w), k=64
        int cp = t & 63, rq = t >> 6;
        u64 aa0[4] = {0,0,0,0}, aa1[4] = {0,0,0,0};
        u64 ae0[4] = {0,0,0,0}, ae1[4] = {0,0,0,0};
        const float* wa0 = Was + cp * 68;
        const float* wa1 = Was + (cp + 64) * 68;
        const float* we0 = ews + cp * 68;
        const float* we1 = ews + (cp + 64) * 68;
#pragma unroll
        for (int d4 = 0; d4 < 16; d4++) {
            float4 a4 = *(const float4*)&wa0[4 * d4];
            float4 b4 = *(const float4*)&wa1[4 * d4];
            float4 c4 = *(const float4*)&we0[4 * d4];
            float4 e4 = *(const float4*)&we1[4 * d4];
            u64 al = lo2(a4), ah = hi2(a4), bl = lo2(b4), bh = hi2(b4);
            u64 cl = lo2(c4), chh = hi2(c4), el = lo2(e4), eh = hi2(e4);
#pragma unroll
            for (int r = 0; r < 4; r++) {
                float4 x4 = *(const float4*)&er[(rq * 4 + r) * 68 + 4 * d4];
                u64 xl = lo2(x4), xh = hi2(x4);
                ffma2(aa0[r], al, xl);  ffma2(aa0[r], ah, xh);
                ffma2(aa1[r], bl, xl);  ffma2(aa1[r], bh, xh);
                ffma2(ae0[r], cl, xl);  ffma2(ae0[r], chh, xh);
                ffma2(ae1[r], el, xl);  ffma2(ae1[r], eh, xh);
            }
        }
        float be0 = et_b[cp], be1 = et_b[cp + 64];
        float lg0[4], lg1[4];
        float lm0 = -3.4e38f, lm1 = -3.4e38f;
#pragma unroll
        for (int r = 0; r < 4; r++) {
            lg0[r] = red2(aa0[r]);
            lg1[r] = red2(aa1[r]);
            int m = m0 + rq * 4 + r;
            if (m < NM) {
                size_t o = ((size_t)b * NM + m) * 128;
                d_logits[o + cp]      = lg0[r];
                d_logits[o + cp + 64] = lg1[r];
                d_etr[o + cp]         = red2(ae0[r]) + be0;
                d_etr[o + cp + 64]    = red2(ae1[r]) + be1;
                lm0 = fmaxf(lm0, lg0[r]);
                lm1 = fmaxf(lm1, lg1[r]);
            }
        }
        float ls0 = 0.f, ls1 = 0.f;
#pragma unroll
        for (int r = 0; r < 4; r++) {
            int m = m0 + rq * 4 + r;
            if (m < NM) {
                ls0 += expf(lg0[r] - lm0);
                ls1 += expf(lg1[r] - lm1);
            }
        }
        redm[cp * 4 + rq]        = lm0;
        reds[cp * 4 + rq]        = ls0;
        redm[(cp + 64) * 4 + rq] = lm1;
        reds[(cp + 64) * 4 + rq] = ls1;
    } else {
        // group B: ntr, k=128 (weights overlaid in Ms)
        int tt = t - 256;
        int cp = tt & 63, rq = tt >> 6;
        u64 an0[4] = {0,0,0,0}, an1[4] = {0,0,0,0};
        const float* wn0 = Ms + cp * 132;
        const float* wn1 = Ms + (cp + 64) * 132;
#pragma unroll 8
        for (int d4 = 0; d4 < 32; d4++) {
            float4 a4 = *(const float4*)&wn0[4 * d4];
            float4 b4 = *(const float4*)&wn1[4 * d4];
            u64 al = lo2(a4), ah = hi2(a4), bl = lo2(b4), bh = hi2(b4);
#pragma unroll
            for (int r = 0; r < 4; r++) {
                float4 x4 = *(const float4*)&nds[(rq * 4 + r) * 128 + 4 * d4];
                u64 xl = lo2(x4), xh = hi2(x4);
                ffma2(an0[r], al, xl); ffma2(an0[r], ah, xh);
                ffma2(an1[r], bl, xl); ffma2(an1[r], bh, xh);
            }
        }
        float bn0 = nt_b[cp], bn1 = nt_b[cp + 64];
#pragma unroll
        for (int r = 0; r < 4; r++) {
            int m = m0 + rq * 4 + r;
            if (m < NM) {
                size_t o = ((size_t)b * NM + m) * 128;
                d_ntr[o + cp]      = red2(an0[r]) + bn0;
                d_ntr[o + cp + 64] = red2(an1[r]) + bn1;
            }
        }
    }
    __syncthreads();

    if (t < 128) {
        int i = t;
        float m = -3.4e38f;
#pragma unroll
        for (int g = 0; g < 4; g++) m = fmaxf(m, redm[i * 4 + g]);
        float s = 0.f;
#pragma unroll
        for (int g = 0; g < 4; g++) s += reds[i * 4 + g] * expf(redm[i * 4 + g] - m);
        d_pm[(b * nblk + ch) * 128 + i] = m;
        d_ps[(b * nblk + ch) * 128 + i] = s;
    }
}

// ---------------------------------------------------------------------------
// K5: fused k5a (softmax combine, alpha, v, h1 gemm+gelu) + k5b (h2 gemm,
//     transposed stores, node_out).
// grid = B*nblk, block = 512
// smem floats (47104 total):
//   H 33280 (h1_w, overlaid by h2_w) | v 4160 | als 2048 | pbuf 2048 |
//   mxs 128 | invs 128 | redm 512 | reds 512 | gs 2112 | qo 2176
// ---------------------------------------------------------------------------
__global__ void __launch_bounds__(512)
k5(const float* __restrict__ h1_w, const float* __restrict__ h1_b,
   const float* __restrict__ h2_w, const float* __restrict__ h2_b,
   float* __restrict__ out_et, float* __restrict__ out_tmp,
   float* __restrict__ out_node, int N, int nblk, float scaler) {
    extern __shared__ float sm[];
    float* H    = sm;
    float* v    = H + 33280;
    float* als  = v + 4160;
    float* pbuf = als + 2048;
    float* mxs  = pbuf + 2048;
    float* invs = mxs + 128;
    float* redm = invs + 128;
    float* reds = redm + 512;
    float* gs   = reds + 512;
    float* qo   = gs + 2112;

    int b  = blockIdx.x / nblk;
    int m0 = (blockIdx.x % nblk) * 16;
    int t  = threadIdx.x;
    int NM = N - 1;

#pragma unroll
    for (int q = t; q < 8192; q += 512) {
        int i = q >> 6, d4 = q & 63;
        *(float4*)&H[i * 260 + 4 * d4] = ((const float4*)h1_w)[q];
    }
    // softmax combine across chunks
    {
        int i = t & 127, cg = t >> 7;
        float m = -3.4e38f, s = 0.f;
        for (int chh = cg; chh < nblk; chh += 4) {
            float pm = d_pm[(b * nblk + chh) * 128 + i];
            float ps = d_ps[(b * nblk + chh) * 128 + i];
            float nm = fmaxf(m, pm);
            s = s * expf(m - nm) + ps * expf(pm - nm);
            m = nm;
        }
        redm[i * 4 + cg] = m;
        reds[i * 4 + cg] = s;
    }
    __syncthreads();
    if (t < 128) {
        int i = t;
        float m = -3.4e38f;
#pragma unroll
        for (int g = 0; g < 4; g++) m = fmaxf(m, redm[i * 4 + g]);
        float s = 0.f;
#pragma unroll
        for (int g = 0; g < 4; g++) s += reds[i * 4 + g] * expf(redm[i * 4 + g] - m);
        mxs[i]  = m;
        invs[i] = 1.f / s;
    }
    __syncthreads();

#pragma unroll
    for (int q = t; q < 2048; q += 512) {
        int r = q >> 7, i = q & 127;
        int m = m0 + r;
        float a = 0.f;
        if (m < NM)
            a = expf(d_logits[((size_t)b * NM + m) * 128 + i] - mxs[i]) * invs[i];
        als[q] = a;
    }
    __syncthreads();
#pragma unroll
    for (int q = t; q < 4096; q += 512) {
        int r = q >> 8, d = q & 255;
        int dd = d & 127;
        int m = m0 + r;
        float val = 0.f;
        if (m < NM) {
            size_t o = ((size_t)b * NM + m) * 128 + dd;
            val = ((d < 128) ? d_etr[o] : d_ntr[o]) * als[r * 128 + dd];
        }
        v[r * 260 + d] = val;
    }
    __syncthreads();

    // et_p store
#pragma unroll
    for (int q = t; q < 2048; q += 512) {
        int i = q >> 4, mr = q & 15;
        int m = m0 + mr;
        if (m < NM) out_et[((size_t)b * 128 + i) * NM + m] = v[mr * 260 + i];
    }

    // h1 GEMM (k=256, split 2, packed) -> gs (smem)
    {
        int kh = t >> 8, tt = t & 255;
        int cp = tt & 63, rq = tt >> 6;
        u64 a0[4] = {0,0,0,0}, a1[4] = {0,0,0,0};
        const float* w0p = H + cp * 260 + kh * 128;
        const float* w1p = H + (cp + 64) * 260 + kh * 128;
        const float* vb  = v + rq * 4 * 260 + kh * 128;
#pragma unroll 8
        for (int d4 = 0; d4 < 32; d4++) {
            float4 w0 = *(const float4*)&w0p[4 * d4];
            float4 w1 = *(const float4*)&w1p[4 * d4];
            u64 w0l = lo2(w0), w0h = hi2(w0), w1l = lo2(w1), w1h = hi2(w1);
#pragma unroll
            for (int r = 0; r < 4; r++) {
                float4 x4 = *(const float4*)&vb[r * 260 + 4 * d4];
                u64 xl = lo2(x4), xh = hi2(x4);
                ffma2(a0[r], w0l, xl); ffma2(a0[r], w0h, xh);
                ffma2(a1[r], w1l, xl); ffma2(a1[r], w1h, xh);
            }
        }
        if (kh == 1) {
#pragma unroll
            for (int r = 0; r < 4; r++) {
                pbuf[(rq * 4 + r) * 128 + cp]      = red2(a0[r]);
                pbuf[(rq * 4 + r) * 128 + cp + 64] = red2(a1[r]);
            }
        }
        __syncthreads();
        if (kh == 0) {
            float b0 = h1_b[cp], b1 = h1_b[cp + 64];
#pragma unroll
            for (int r = 0; r < 4; r++) {
                int rw = rq * 4 + r;
                int m = m0 + rw;
                float g0 = red2(a0[r]) + pbuf[rw * 128 + cp] + b0;
                float g1 = red2(a1[r]) + pbuf[rw * 128 + cp + 64] + b1;
                gs[rw * 132 + cp]      = (m < NM) ? geluf(g0) : 0.f;
                gs[rw * 132 + cp + 64] = (m < NM) ? geluf(g1) : 0.f;
            }
        }
        __syncthreads();
    }

    // overlay h2_w into H
#pragma unroll
    for (int q = t; q < 4096; q += 512) {
        int i = q >> 5, d4 = q & 31;
        *(float4*)&H[i * 132 + 4 * d4] = ((const float4*)h2_w)[q];
    }
    __syncthreads();

    // h2 GEMM (k=128, split 2, packed) -> qo
    {
        int kh = t >> 8, tt = t & 255;
        int cp = tt & 63, rq = tt >> 6;
        u64 a0[4] = {0,0,0,0}, a1[4] = {0,0,0,0};
        const float* w0p = H + cp * 132 + kh * 64;
        const float* w1p = H + (cp + 64) * 132 + kh * 64;
        const float* gb  = gs + rq * 4 * 132 + kh * 64;
#pragma unroll
        for (int d4 = 0; d4 < 16; d4++) {
            float4 w0 = *(const float4*)&w0p[4 * d4];
            float4 w1 = *(const float4*)&w1p[4 * d4];
            u64 w0l = lo2(w0), w0h = hi2(w0), w1l = lo2(w1), w1h = hi2(w1);
#pragma unroll
            for (int r = 0; r < 4; r++) {
                float4 x4 = *(const float4*)&gb[r * 132 + 4 * d4];
                u64 xl = lo2(x4), xh = hi2(x4);
                ffma2(a0[r], w0l, xl); ffma2(a0[r], w0h, xh);
                ffma2(a1[r], w1l, xl); ffma2(a1[r], w1h, xh);
            }
        }
        if (kh == 1) {
#pragma unroll
            for (int r = 0; r < 4; r++) {
                pbuf[(rq * 4 + r) * 128 + cp]      = red2(a0[r]);
                pbuf[(rq * 4 + r) * 128 + cp + 64] = red2(a1[r]);
            }
        }
        __syncthreads();
        if (kh == 0) {
            float b0 = h2_b[cp], b1 = h2_b[cp + 64];
#pragma unroll
            for (int r = 0; r < 4; r++) {
                int rw = rq * 4 + r;
                int m = m0 + rw;
                float t0 = (m < NM) ? red2(a0[r]) + pbuf[rw * 128 + cp] + b0 : 0.f;
                float t1 = (m < NM) ? red2(a1[r]) + pbuf[rw * 128 + cp + 64] + b1 : 0.f;
                qo[cp * 17 + rw]        = t0;
                qo[(cp + 64) * 17 + rw] = t1;
            }
        }
        __syncthreads();
    }

    // transposed tmp_p store
#pragma unroll
    for (int q = t; q < 2048; q += 512) {
        int i = q >> 4, mr = q & 15;
        int m = m0 + mr;
        if (m < NM) out_tmp[((size_t)b * 128 + i) * NM + m] = qo[i * 17 + mr];
    }
    // node_out partial
    if (t < 128) {
        int i = t;
        float s = 0.f;
#pragma unroll
        for (int mr = 0; mr < 16; mr++) s += qo[i * 17 + mr];
        atomicAdd(&out_node[b * 128 + i], s * scaler);
    }
}

// ---------------------------------------------------------------------------
extern "C" void kernel_launch(void* const* d_in, const int* in_sizes, int n_in,
                              void* d_out, int out_size) {
    const float* node = (const float*)d_in[0];
    const float* edge = (const float*)d_in[1];
    const float* emb  = (const float*)d_in[2];
    const float* Wq_w = (const float*)d_in[3];
    const float* Wq_b = (const float*)d_in[4];
    const float* Wk_w = (const float*)d_in[5];
    const float* Wk_b = (const float*)d_in[6];
    const float* Wew  = (const float*)d_in[7];
    const float* Web  = (const float*)d_in[8];
    const float* Wa   = (const float*)d_in[9];
    const float* nt_w = (const float*)d_in[10];
    const float* nt_b = (const float*)d_in[11];
    const float* et_w = (const float*)d_in[12];
    const float* et_b = (const float*)d_in[13];
    const float* h1_w = (const float*)d_in[14];
    const float* h1_b = (const float*)d_in[15];
    const float* h2_w = (const float*)d_in[16];
    const float* h2_b = (const float*)d_in[17];

    long n_node = in_sizes[0];
    long n_edge = in_sizes[1];
    int N = (int)((2L * n_edge) / n_node);   // 512
    int B = (int)(n_node / ((long)N * 128)); // 4
    int NM = N - 1;
    int nblk = (NM + 15) / 16;               // 32

    float* out      = (float*)d_out;
    float* out_node = out;
    float* out_tmp  = out + (size_t)B * 128;
    float* out_et   = out_tmp + (size_t)B * 128 * NM;

    const int SM23 = 53440 * 4;
    const int SM5  = 47104 * 4;

    cudaFuncSetAttribute(k23, cudaFuncAttributeMaxDynamicSharedMemorySize, SM23);
    cudaFuncSetAttribute(k5,  cudaFuncAttributeMaxDynamicSharedMemorySize, SM5);

    float scaler = 2.0f / sqrtf(128.0f);

    k1_fold<<<B * 8, 128>>>(node, Wq_w, Wq_b, Wk_w, Wk_b, out_node, B, N);
    k23<<<B * nblk, 512, SM23>>>(node, edge, emb, Wew, Web, Wa,
                                 nt_w, nt_b, et_w, et_b, N, nblk);
    k5<<<B * nblk, 512, SM5>>>(h1_w, h1_b, h2_w, h2_b,
                               out_et, out_tmp, out_node, N, nblk, scaler);
}

// round 5
// speedup vs baseline: 4.0945x; 1.3406x over previous
#include <cuda_runtime.h>
#include <math.h>

// Fixed problem dims (B=4, N=512, C=128, ED=64, ATT=8, IN=128)
#define MAXB 4
#define MAXNM 511
#define MAXCH 32

typedef unsigned long long u64;

// ---------------- scratch (device globals) ----------------
__device__ float d_M[MAXB * 128 * 128];
__device__ float d_c[MAXB * 128];
__device__ float d_logits[MAXB * MAXNM * 128];
__device__ float d_etr[MAXB * MAXNM * 128];
__device__ float d_ntr[MAXB * MAXNM * 128];
__device__ float d_pm[MAXB * MAXCH * 128];
__device__ float d_ps[MAXB * MAXCH * 128];

__device__ __forceinline__ float geluf(float x) {
    return 0.5f * x * (1.0f + erff(x * 0.7071067811865476f));
}
__device__ __forceinline__ float rhof(float x) {
    return copysignf(sqrtf(fabsf(x)), x);
}
__device__ __forceinline__ void ffma2(u64& acc, u64 a, u64 b) {
    asm("fma.rn.f32x2 %0, %1, %2, %0;" : "+l"(acc) : "l"(a), "l"(b));
}
__device__ __forceinline__ u64 lo2(const float4& v) { return *(const u64*)&v.x; }
__device__ __forceinline__ u64 hi2(const float4& v) { return *(const u64*)&v.z; }
__device__ __forceinline__ float red2(u64 v) {
    return __uint_as_float((unsigned)v) + __uint_as_float((unsigned)(v >> 32));
}
__device__ __forceinline__ float dot4(float4 a, float4 b) {
    return a.x * b.x + a.y * b.y + a.z * b.z + a.w * b.w;
}

// ---------------------------------------------------------------------------
// K1: fold q into M[b,e,d], c[b,e]; zero out_node.
// grid = B*128 (one block per (b,e)), block = 128 (4 warps)
// ---------------------------------------------------------------------------
__global__ void k1_fold(const float* __restrict__ node,
                        const float* __restrict__ Wq_w, const float* __restrict__ Wq_b,
                        const float* __restrict__ Wk_w, const float* __restrict__ Wk_b,
                        float* __restrict__ out_node, int B, int N) {
    int b = blockIdx.x >> 7;
    int e = blockIdx.x & 127;
    int t = threadIdx.x;
    int lane = t & 31, w = t >> 5;

    if (blockIdx.x < B) out_node[blockIdx.x * 128 + t] = 0.f;

    __shared__ float nd0[128];
    __shared__ float qv[8];

    nd0[t] = node[(size_t)b * N * 128 + t];
    __syncthreads();

    float4 n4 = *(const float4*)&nd0[lane * 4];
#pragma unroll
    for (int aa = 0; aa < 2; aa++) {
        int a = w + aa * 4;
        int row = (a << 7) + e;
        float4 v4 = *(const float4*)&Wq_w[(size_t)row * 128 + lane * 4];
        float acc = dot4(v4, n4);
#pragma unroll
        for (int o = 16; o > 0; o >>= 1) acc += __shfl_down_sync(0xffffffffu, acc, o);
        if (lane == 0) qv[a] = acc + Wq_b[row];
    }
    __syncthreads();

    float q0 = qv[0], q1 = qv[1], q2 = qv[2], q3 = qv[3];
    float q4 = qv[4], q5 = qv[5], q6 = qv[6], q7 = qv[7];

    const float* wk = Wk_w + e * 128 + t;
    float acc = q0 * wk[0]
              + q1 * wk[128 * 128]
              + q2 * wk[2 * 128 * 128]
              + q3 * wk[3 * 128 * 128]
              + q4 * wk[(size_t)4 * 128 * 128]
              + q5 * wk[(size_t)5 * 128 * 128]
              + q6 * wk[(size_t)6 * 128 * 128]
              + q7 * wk[(size_t)7 * 128 * 128];
    d_M[(size_t)b * 16384 + e * 128 + t] = acc;

    if (t == 0) {
        float c = 0.f;
#pragma unroll
        for (int a = 0; a < 8; a++) c += qv[a] * Wk_b[(a << 7) + e];
        d_c[b * 128 + e] = c;
    }
}

// ---------------------------------------------------------------------------
// K23: fused k2 (qk + edge gelu) and k3 (logits/etr/ntr + softmax partials)
// grid = B*nblk, block = 512
// ---------------------------------------------------------------------------
__global__ void __launch_bounds__(512)
k23(const float* __restrict__ node,
    const float* __restrict__ edge,
    const float* __restrict__ emb,
    const float* __restrict__ Wew,
    const float* __restrict__ Web,
    const float* __restrict__ Wa,
    const float* __restrict__ nt_w, const float* __restrict__ nt_b,
    const float* __restrict__ et_w, const float* __restrict__ et_b,
    int N, int nblk) {
    extern __shared__ float sm[];
    float* Ms   = sm;
    float* Wes  = Ms + 16896;
    float* Wbs  = Wes + 4352;
    float* Was  = Wbs + 4352;
    float* ews  = Was + 8704;
    float* nds  = ews + 8704;
    float* e0s  = nds + 2048;
    float* ems  = e0s + 1024;
    float* cs   = ems + 1024;
    float* qks  = cs + 128;
    float* pbuf = qks + 2048;
    float* er   = pbuf + 2048;
    float* redm = er + 1088;
    float* reds = redm + 512;

    int b  = blockIdx.x / nblk;
    int ch = blockIdx.x % nblk;
    int m0 = ch * 16;
    int t  = threadIdx.x;
    int NM = N - 1;

    // ---- phase 0: loads ----
    {
        const float4* src = (const float4*)(d_M + (size_t)b * 16384);
#pragma unroll
        for (int q = t; q < 4096; q += 512) {
            int e = q >> 5, d4 = q & 31;
            *(float4*)&Ms[e * 132 + 4 * d4] = src[q];
        }
    }
#pragma unroll
    for (int q = t; q < 1024; q += 512) {
        int j = q >> 4, d4 = q & 15;
        *(float4*)&Wes[j * 68 + 4 * d4] = ((const float4*)Wew)[q];
        *(float4*)&Wbs[j * 68 + 4 * d4] = ((const float4*)Web)[q];
    }
#pragma unroll
    for (int q = t; q < 2048; q += 512) {
        int i = q >> 4, d4 = q & 15;
        *(float4*)&Was[i * 68 + 4 * d4] = ((const float4*)Wa)[q];
        *(float4*)&ews[i * 68 + 4 * d4] = ((const float4*)et_w)[q];
    }
    if (t < 128) cs[t] = d_c[b * 128 + t];
    {
        int r = t >> 5, d4 = t & 31;
        int m = m0 + r;
        float4 v = make_float4(0.f, 0.f, 0.f, 0.f);
        if (m < NM) v = *(const float4*)&node[((size_t)b * N + m + 1) * 128 + 4 * d4];
        *(float4*)&nds[r * 128 + 4 * d4] = v;
    }
    {
        int q = t & 255;
        int r = q >> 4, d4 = q & 15;
        int m = m0 + r;
        float4 v = make_float4(0.f, 0.f, 0.f, 0.f);
        if (m < NM) {
            size_t base = ((size_t)b * N * N + (size_t)(m + 1)) * 64 + 4 * d4;
            v = (t < 256) ? *(const float4*)&edge[base] : *(const float4*)&emb[base];
        }
        if (t < 256) *(float4*)&e0s[r * 64 + 4 * d4] = v;
        else         *(float4*)&ems[r * 64 + 4 * d4] = v;
    }
    __syncthreads();

    // ---- phase A: qk (k-split 2, packed fma) ----
    {
        int kh = t >> 8, tt = t & 255;
        int cp = tt & 63, rq = tt >> 6;
        u64 a0[4] = {0,0,0,0}, a1[4] = {0,0,0,0};
        const float* m0p = Ms + cp * 132 + kh * 64;
        const float* m1p = Ms + (cp + 64) * 132 + kh * 64;
        const float* nb  = nds + rq * 4 * 128 + kh * 64;
#pragma unroll
        for (int d4 = 0; d4 < 16; d4++) {
            float4 ma = *(const float4*)&m0p[4 * d4];
            float4 mb = *(const float4*)&m1p[4 * d4];
            u64 mal = lo2(ma), mah = hi2(ma), mbl = lo2(mb), mbh = hi2(mb);
#pragma unroll
            for (int r = 0; r < 4; r++) {
                float4 n4 = *(const float4*)&nb[r * 128 + 4 * d4];
                u64 nl = lo2(n4), nh = hi2(n4);
                ffma2(a0[r], mal, nl); ffma2(a0[r], mah, nh);
                ffma2(a1[r], mbl, nl); ffma2(a1[r], mbh, nh);
            }
        }
        if (kh == 1) {
#pragma unroll
            for (int r = 0; r < 4; r++) {
                pbuf[(rq * 4 + r) * 128 + cp]      = red2(a0[r]);
                pbuf[(rq * 4 + r) * 128 + cp + 64] = red2(a1[r]);
            }
        }
        __syncthreads();
        if (kh == 0) {
            float c0 = cs[cp], c1 = cs[cp + 64];
#pragma unroll
            for (int r = 0; r < 4; r++) {
                int rw = rq * 4 + r;
                qks[rw * 128 + cp]      = red2(a0[r]) + pbuf[rw * 128 + cp] + c0;
                qks[rw * 128 + cp + 64] = red2(a1[r]) + pbuf[rw * 128 + cp + 64] + c1;
            }
        }
        __syncthreads();
    }

    // ---- phase B: edge projections + gelu -> er (smem) ----
    {
        int j = t & 63, rg = t >> 6;
        u64 ew2[2] = {0, 0}, eb2[2] = {0, 0};
        const float* wrow = Wes + j * 68;
        const float* brow = Wbs + j * 68;
#pragma unroll
        for (int d4 = 0; d4 < 16; d4++) {
            float4 w4 = *(const float4*)&wrow[4 * d4];
            float4 b4 = *(const float4*)&brow[4 * d4];
            u64 wl = lo2(w4), wh = hi2(w4), bl = lo2(b4), bh = hi2(b4);
#pragma unroll
            for (int r = 0; r < 2; r++) {
                float4 x4 = *(const float4*)&e0s[(rg * 2 + r) * 64 + 4 * d4];
                u64 xl = lo2(x4), xh = hi2(x4);
                ffma2(ew2[r], wl, xl); ffma2(ew2[r], wh, xh);
                ffma2(eb2[r], bl, xl); ffma2(eb2[r], bh, xh);
            }
        }
#pragma unroll
        for (int r = 0; r < 2; r++) {
            int rr = rg * 2 + r;
            int m = m0 + rr;
            float val = 0.f;
            if (m < NM) {
                float x = rhof(qks[rr * 128 + j] * red2(ew2[r])) + red2(eb2[r])
                        + qks[rr * 128 + 64 + j] + ems[rr * 64 + j];
                val = geluf(x);
            }
            er[rr * 68 + j] = val;
        }
    }
    __syncthreads();

    // ---- overlay nt_w into Ms region ----
#pragma unroll
    for (int q = t; q < 4096; q += 512) {
        int i = q >> 5, d4 = q & 31;
        *(float4*)&Ms[i * 132 + 4 * d4] = ((const float4*)nt_w)[q];
    }
    __syncthreads();

    // ---- phase C: k3 ----
    if (t < 256) {
        int cp = t & 63, rq = t >> 6;
        u64 aa0[4] = {0,0,0,0}, aa1[4] = {0,0,0,0};
        u64 ae0[4] = {0,0,0,0}, ae1[4] = {0,0,0,0};
        const float* wa0 = Was + cp * 68;
        const float* wa1 = Was + (cp + 64) * 68;
        const float* we0 = ews + cp * 68;
        const float* we1 = ews + (cp + 64) * 68;
#pragma unroll
        for (int d4 = 0; d4 < 16; d4++) {
            float4 a4 = *(const float4*)&wa0[4 * d4];
            float4 b4 = *(const float4*)&wa1[4 * d4];
            float4 c4 = *(const float4*)&we0[4 * d4];
            float4 e4 = *(const float4*)&we1[4 * d4];
            u64 al = lo2(a4), ah = hi2(a4), bl = lo2(b4), bh = hi2(b4);
            u64 cl = lo2(c4), chh = hi2(c4), el = lo2(e4), eh = hi2(e4);
#pragma unroll
            for (int r = 0; r < 4; r++) {
                float4 x4 = *(const float4*)&er[(rq * 4 + r) * 68 + 4 * d4];
                u64 xl = lo2(x4), xh = hi2(x4);
                ffma2(aa0[r], al, xl);  ffma2(aa0[r], ah, xh);
                ffma2(aa1[r], bl, xl);  ffma2(aa1[r], bh, xh);
                ffma2(ae0[r], cl, xl);  ffma2(ae0[r], chh, xh);
                ffma2(ae1[r], el, xl);  ffma2(ae1[r], eh, xh);
            }
        }
        float be0 = et_b[cp], be1 = et_b[cp + 64];
        float lg0[4], lg1[4];
        float lm0 = -3.4e38f, lm1 = -3.4e38f;
#pragma unroll
        for (int r = 0; r < 4; r++) {
            lg0[r] = red2(aa0[r]);
            lg1[r] = red2(aa1[r]);
            int m = m0 + rq * 4 + r;
            if (m < NM) {
                size_t o = ((size_t)b * NM + m) * 128;
                d_logits[o + cp]      = lg0[r];
                d_logits[o + cp + 64] = lg1[r];
                d_etr[o + cp]         = red2(ae0[r]) + be0;
                d_etr[o + cp + 64]    = red2(ae1[r]) + be1;
                lm0 = fmaxf(lm0, lg0[r]);
                lm1 = fmaxf(lm1, lg1[r]);
            }
        }
        float ls0 = 0.f, ls1 = 0.f;
#pragma unroll
        for (int r = 0; r < 4; r++) {
            int m = m0 + rq * 4 + r;
            if (m < NM) {
                ls0 += expf(lg0[r] - lm0);
                ls1 += expf(lg1[r] - lm1);
            }
        }
        redm[cp * 4 + rq]        = lm0;
        reds[cp * 4 + rq]        = ls0;
        redm[(cp + 64) * 4 + rq] = lm1;
        reds[(cp + 64) * 4 + rq] = ls1;
    } else {
        int tt = t - 256;
        int cp = tt & 63, rq = tt >> 6;
        u64 an0[4] = {0,0,0,0}, an1[4] = {0,0,0,0};
        const float* wn0 = Ms + cp * 132;
        const float* wn1 = Ms + (cp + 64) * 132;
#pragma unroll 8
        for (int d4 = 0; d4 < 32; d4++) {
            float4 a4 = *(const float4*)&wn0[4 * d4];
            float4 b4 = *(const float4*)&wn1[4 * d4];
            u64 al = lo2(a4), ah = hi2(a4), bl = lo2(b4), bh = hi2(b4);
#pragma unroll
            for (int r = 0; r < 4; r++) {
                float4 x4 = *(const float4*)&nds[(rq * 4 + r) * 128 + 4 * d4];
                u64 xl = lo2(x4), xh = hi2(x4);
                ffma2(an0[r], al, xl); ffma2(an0[r], ah, xh);
                ffma2(an1[r], bl, xl); ffma2(an1[r], bh, xh);
            }
        }
        float bn0 = nt_b[cp], bn1 = nt_b[cp + 64];
#pragma unroll
        for (int r = 0; r < 4; r++) {
            int m = m0 + rq * 4 + r;
            if (m < NM) {
                size_t o = ((size_t)b * NM + m) * 128;
                d_ntr[o + cp]      = red2(an0[r]) + bn0;
                d_ntr[o + cp + 64] = red2(an1[r]) + bn1;
            }
        }
    }
    __syncthreads();

    if (t < 128) {
        int i = t;
        float m = -3.4e38f;
#pragma unroll
        for (int g = 0; g < 4; g++) m = fmaxf(m, redm[i * 4 + g]);
        float s = 0.f;
#pragma unroll
        for (int g = 0; g < 4; g++) s += reds[i * 4 + g] * expf(redm[i * 4 + g] - m);
        d_pm[(b * nblk + ch) * 128 + i] = m;
        d_ps[(b * nblk + ch) * 128 + i] = s;
    }
}

// ---------------------------------------------------------------------------
// K5: fused softmax combine + alpha + v + h1 gemm/gelu + h2 gemm + stores
// grid = B*nblk, block = 512
// ---------------------------------------------------------------------------
__global__ void __launch_bounds__(512)
k5(const float* __restrict__ h1_w, const float* __restrict__ h1_b,
   const float* __restrict__ h2_w, const float* __restrict__ h2_b,
   float* __restrict__ out_et, float* __restrict__ out_tmp,
   float* __restrict__ out_node, int N, int nblk, float scaler) {
    extern __shared__ float sm[];
    float* H    = sm;
    float* v    = H + 33280;
    float* als  = v + 4160;
    float* pbuf = als + 2048;
    float* mxs  = pbuf + 2048;
    float* invs = mxs + 128;
    float* redm = invs + 128;
    float* reds = redm + 512;
    float* gs   = reds + 512;
    float* qo   = gs + 2112;

    int b  = blockIdx.x / nblk;
    int m0 = (blockIdx.x % nblk) * 16;
    int t  = threadIdx.x;
    int NM = N - 1;

#pragma unroll
    for (int q = t; q < 8192; q += 512) {
        int i = q >> 6, d4 = q & 63;
        *(float4*)&H[i * 260 + 4 * d4] = ((const float4*)h1_w)[q];
    }
    {
        int i = t & 127, cg = t >> 7;
        float m = -3.4e38f, s = 0.f;
        for (int chh = cg; chh < nblk; chh += 4) {
            float pm = d_pm[(b * nblk + chh) * 128 + i];
            float ps = d_ps[(b * nblk + chh) * 128 + i];
            float nm = fmaxf(m, pm);
            s = s * expf(m - nm) + ps * expf(pm - nm);
            m = nm;
        }
        redm[i * 4 + cg] = m;
        reds[i * 4 + cg] = s;
    }
    __syncthreads();
    if (t < 128) {
        int i = t;
        float m = -3.4e38f;
#pragma unroll
        for (int g = 0; g < 4; g++) m = fmaxf(m, redm[i * 4 + g]);
        float s = 0.f;
#pragma unroll
        for (int g = 0; g < 4; g++) s += reds[i * 4 + g] * expf(redm[i * 4 + g] - m);
        mxs[i]  = m;
        invs[i] = 1.f / s;
    }
    __syncthreads();

#pragma unroll
    for (int q = t; q < 2048; q += 512) {
        int r = q >> 7, i = q & 127;
        int m = m0 + r;
        float a = 0.f;
        if (m < NM)
            a = expf(d_logits[((size_t)b * NM + m) * 128 + i] - mxs[i]) * invs[i];
        als[q] = a;
    }
    __syncthreads();
#pragma unroll
    for (int q = t; q < 4096; q += 512) {
        int r = q >> 8, d = q & 255;
        int dd = d & 127;
        int m = m0 + r;
        float val = 0.f;
        if (m < NM) {
            size_t o = ((size_t)b * NM + m) * 128 + dd;
            val = ((d < 128) ? d_etr[o] : d_ntr[o]) * als[r * 128 + dd];
        }
        v[r * 260 + d] = val;
    }
    __syncthreads();

#pragma unroll
    for (int q = t; q < 2048; q += 512) {
        int i = q >> 4, mr = q & 15;
        int m = m0 + mr;
        if (m < NM) out_et[((size_t)b * 128 + i) * NM + m] = v[mr * 260 + i];
    }

    // h1 GEMM (k=256, split 2, packed) -> gs
    {
        int kh = t >> 8, tt = t & 255;
        int cp = tt & 63, rq = tt >> 6;
        u64 a0[4] = {0,0,0,0}, a1[4] = {0,0,0,0};
        const float* w0p = H + cp * 260 + kh * 128;
        const float* w1p = H + (cp + 64) * 260 + kh * 128;
        const float* vb  = v + rq * 4 * 260 + kh * 128;
#pragma unroll 8
        for (int d4 = 0; d4 < 32; d4++) {
            float4 w0 = *(const float4*)&w0p[4 * d4];
            float4 w1 = *(const float4*)&w1p[4 * d4];
            u64 w0l = lo2(w0), w0h = hi2(w0), w1l = lo2(w1), w1h = hi2(w1);
#pragma unroll
            for (int r = 0; r < 4; r++) {
                float4 x4 = *(const float4*)&vb[r * 260 + 4 * d4];
                u64 xl = lo2(x4), xh = hi2(x4);
                ffma2(a0[r], w0l, xl); ffma2(a0[r], w0h, xh);
                ffma2(a1[r], w1l, xl); ffma2(a1[r], w1h, xh);
            }
        }
        if (kh == 1) {
#pragma unroll
            for (int r = 0; r < 4; r++) {
                pbuf[(rq * 4 + r) * 128 + cp]      = red2(a0[r]);
                pbuf[(rq * 4 + r) * 128 + cp + 64] = red2(a1[r]);
            }
        }
        __syncthreads();
        if (kh == 0) {
            float b0 = h1_b[cp], b1 = h1_b[cp + 64];
#pragma unroll
            for (int r = 0; r < 4; r++) {
                int rw = rq * 4 + r;
                int m = m0 + rw;
                float g0 = red2(a0[r]) + pbuf[rw * 128 + cp] + b0;
                float g1 = red2(a1[r]) + pbuf[rw * 128 + cp + 64] + b1;
                gs[rw * 132 + cp]      = (m < NM) ? geluf(g0) : 0.f;
                gs[rw * 132 + cp + 64] = (m < NM) ? geluf(g1) : 0.f;
            }
        }
        __syncthreads();
    }

    // overlay h2_w into H
#pragma unroll
    for (int q = t; q < 4096; q += 512) {
        int i = q >> 5, d4 = q & 31;
        *(float4*)&H[i * 132 + 4 * d4] = ((const float4*)h2_w)[q];
    }
    __syncthreads();

    // h2 GEMM (k=128, split 2, packed) -> qo
    {
        int kh = t >> 8, tt = t & 255;
        int cp = tt & 63, rq = tt >> 6;
        u64 a0[4] = {0,0,0,0}, a1[4] = {0,0,0,0};
        const float* w0p = H + cp * 132 + kh * 64;
        const float* w1p = H + (cp + 64) * 132 + kh * 64;
        const float* gb  = gs + rq * 4 * 132 + kh * 64;
#pragma unroll
        for (int d4 = 0; d4 < 16; d4++) {
            float4 w0 = *(const float4*)&w0p[4 * d4];
            float4 w1 = *(const float4*)&w1p[4 * d4];
            u64 w0l = lo2(w0), w0h = hi2(w0), w1l = lo2(w1), w1h = hi2(w1);
#pragma unroll
            for (int r = 0; r < 4; r++) {
                float4 x4 = *(const float4*)&gb[r * 132 + 4 * d4];
                u64 xl = lo2(x4), xh = hi2(x4);
                ffma2(a0[r], w0l, xl); ffma2(a0[r], w0h, xh);
                ffma2(a1[r], w1l, xl); ffma2(a1[r], w1h, xh);
            }
        }
        if (kh == 1) {
#pragma unroll
            for (int r = 0; r < 4; r++) {
                pbuf[(rq * 4 + r) * 128 + cp]      = red2(a0[r]);
                pbuf[(rq * 4 + r) * 128 + cp + 64] = red2(a1[r]);
            }
        }
        __syncthreads();
        if (kh == 0) {
            float b0 = h2_b[cp], b1 = h2_b[cp + 64];
#pragma unroll
            for (int r = 0; r < 4; r++) {
                int rw = rq * 4 + r;
                int m = m0 + rw;
                float t0 = (m < NM) ? red2(a0[r]) + pbuf[rw * 128 + cp] + b0 : 0.f;
                float t1 = (m < NM) ? red2(a1[r]) + pbuf[rw * 128 + cp + 64] + b1 : 0.f;
                qo[cp * 17 + rw]        = t0;
                qo[(cp + 64) * 17 + rw] = t1;
            }
        }
        __syncthreads();
    }

#pragma unroll
    for (int q = t; q < 2048; q += 512) {
        int i = q >> 4, mr = q & 15;
        int m = m0 + mr;
        if (m < NM) out_tmp[((size_t)b * 128 + i) * NM + m] = qo[i * 17 + mr];
    }
    if (t < 128) {
        int i = t;
        float s = 0.f;
#pragma unroll
        for (int mr = 0; mr < 16; mr++) s += qo[i * 17 + mr];
        atomicAdd(&out_node[b * 128 + i], s * scaler);
    }
}

// ---------------------------------------------------------------------------
extern "C" void kernel_launch(void* const* d_in, const int* in_sizes, int n_in,
                              void* d_out, int out_size) {
    const float* node = (const float*)d_in[0];
    const float* edge = (const float*)d_in[1];
    const float* emb  = (const float*)d_in[2];
    const float* Wq_w = (const float*)d_in[3];
    const float* Wq_b = (const float*)d_in[4];
    const float* Wk_w = (const float*)d_in[5];
    const float* Wk_b = (const float*)d_in[6];
    const float* Wew  = (const float*)d_in[7];
    const float* Web  = (const float*)d_in[8];
    const float* Wa   = (const float*)d_in[9];
    const float* nt_w = (const float*)d_in[10];
    const float* nt_b = (const float*)d_in[11];
    const float* et_w = (const float*)d_in[12];
    const float* et_b = (const float*)d_in[13];
    const float* h1_w = (const float*)d_in[14];
    const float* h1_b = (const float*)d_in[15];
    const float* h2_w = (const float*)d_in[16];
    const float* h2_b = (const float*)d_in[17];

    long n_node = in_sizes[0];
    long n_edge = in_sizes[1];
    int N = (int)((2L * n_edge) / n_node);   // 512
    int B = (int)(n_node / ((long)N * 128)); // 4
    int NM = N - 1;
    int nblk = (NM + 15) / 16;               // 32

    float* out      = (float*)d_out;
    float* out_node = out;
    float* out_tmp  = out + (size_t)B * 128;
    float* out_et   = out_tmp + (size_t)B * 128 * NM;

    const int SM23 = 53440 * 4;
    const int SM5  = 47104 * 4;

    cudaFuncSetAttribute(k23, cudaFuncAttributeMaxDynamicSharedMemorySize, SM23);
    cudaFuncSetAttribute(k5,  cudaFuncAttributeMaxDynamicSharedMemorySize, SM5);

    float scaler = 2.0f / sqrtf(128.0f);

    k1_fold<<<B * 128, 128>>>(node, Wq_w, Wq_b, Wk_w, Wk_b, out_node, B, N);
    k23<<<B * nblk, 512, SM23>>>(node, edge, emb, Wew, Web, Wa,
                                 nt_w, nt_b, et_w, et_b, N, nblk);
    k5<<<B * nblk, 512, SM5>>>(h1_w, h1_b, h2_w, h2_b,
                               out_et, out_tmp, out_node, N, nblk, scaler);
}